// round 11
// baseline (speedup 1.0000x reference)
#include <cuda_runtime.h>
#include <cuda_bf16.h>
#include <cuda_fp16.h>
#include <cstdint>

// Problem constants
#define NMAX 100000
#define EMAX 800000
#define HPAD 100096   // NMAX rounded up to 128 (tile padding)

// Scratch (no allocation allowed -> __device__ globals)
__device__ float g_xl[NMAX * 128];     // fp16 xl (half2) buffers
__device__ float g_xr[NMAX * 128];     // fp32 xr
__device__ __align__(16) unsigned char g_hhi[HPAD * 128];  // h bf16-hi image (swizzled)
__device__ __align__(16) unsigned char g_hlo[HPAD * 128];  // h bf16-lo image (swizzled)
__device__ int   g_cnt[NMAX];
__device__ int   g_rowptr[NMAX + 1];
__device__ int   g_fill[NMAX];
__device__ int   g_adj[EMAX];
__device__ int   g_bsum[128];
// bf16 [n=128][k=64] W images (XOR-swizzled): 0:[W1l|W1r] 1:[W2l|W2r] 2:W3l 3:W3r
__device__ __align__(16) unsigned char g_wimg_hi[4][16384];
__device__ __align__(16) unsigned char g_wimg_lo[4][16384];

// ---------------------------------------------------------------------------
// helpers
// ---------------------------------------------------------------------------
__device__ __forceinline__ uint32_t smem_u32(const void* p) {
    uint32_t a;
    asm("{ .reg .u64 t; cvta.to.shared.u64 t, %1; cvt.u32.u64 %0, t; }" : "=r"(a) : "l"(p));
    return a;
}
__device__ __forceinline__ void bf16_split(float v, uint16_t& hi, uint16_t& lo) {
    __nv_bfloat16 h = __float2bfloat16(v);
    float residual = v - __bfloat162float(h);
    __nv_bfloat16 l = __float2bfloat16(residual);
    hi = *(uint16_t*)&h;
    lo = *(uint16_t*)&l;
}
__device__ __forceinline__ void ldm_x4(uint32_t (&r)[4], uint32_t addr) {
    asm volatile("ldmatrix.sync.aligned.m8n8.x4.shared.b16 {%0,%1,%2,%3}, [%4];"
                 : "=r"(r[0]), "=r"(r[1]), "=r"(r[2]), "=r"(r[3]) : "r"(addr));
}
__device__ __forceinline__ void mma_bf16(float (&d)[4], const uint32_t (&a)[4],
                                         uint32_t b0, uint32_t b1) {
    asm volatile(
        "mma.sync.aligned.m16n8k16.row.col.f32.bf16.bf16.f32 "
        "{%0,%1,%2,%3}, {%4,%5,%6,%7}, {%8,%9}, {%0,%1,%2,%3};"
        : "+f"(d[0]), "+f"(d[1]), "+f"(d[2]), "+f"(d[3])
        : "r"(a[0]), "r"(a[1]), "r"(a[2]), "r"(a[3]), "r"(b0), "r"(b1));
}
// XOR swizzle inside a 128B row: 16B chunk index XORed with (row&7)
__device__ __forceinline__ uint32_t swz_off(int row, int byte_in_row) {
    return (uint32_t)(row * 128 + (byte_in_row ^ ((row & 7) << 4)));
}

// ---------------------------------------------------------------------------
// k_init: zero cnt + bsum, W -> bf16 hi/lo images
// ---------------------------------------------------------------------------
__global__ void k_init(const float* __restrict__ W1l, const float* __restrict__ W1r,
                       const float* __restrict__ W2l, const float* __restrict__ W2r,
                       const float* __restrict__ W3l, const float* __restrict__ W3r,
                       int N) {
    if (blockIdx.x >= 64) {
        int i = (blockIdx.x - 64) * 256 + threadIdx.x;
        if (i < N) g_cnt[i] = 0;
        if (blockIdx.x == 64 && threadIdx.x < 128) g_bsum[threadIdx.x] = 0;
        return;
    }
    int tid = blockIdx.x * 256 + threadIdx.x;   // 0..16383
    int img = tid >> 12, idx = tid & 4095;
    int n = idx >> 5, kp = idx & 31;
    int k0 = 2 * kp, k1 = k0 + 1;
    float v0, v1;
    if (img == 0) {
        v0 = (n < 64) ? W1l[k0 * 64 + n] : W1r[k0 * 64 + n - 64];
        v1 = (n < 64) ? W1l[k1 * 64 + n] : W1r[k1 * 64 + n - 64];
    } else if (img == 1) {
        v0 = (n < 64) ? W2l[k0 * 64 + n] : W2r[k0 * 64 + n - 64];
        v1 = (n < 64) ? W2l[k1 * 64 + n] : W2r[k1 * 64 + n - 64];
    } else if (img == 2) {
        v0 = W3l[k0 * 128 + n];
        v1 = W3l[k1 * 128 + n];
    } else {
        v0 = W3r[k0 * 128 + n];
        v1 = W3r[k1 * 128 + n];
    }
    uint16_t h0, l0, h1, l1;
    bf16_split(v0, h0, l0);
    bf16_split(v1, h1, l1);
    uint32_t off = swz_off(n, kp * 4);
    *(uint32_t*)(g_wimg_hi[img] + off) = (uint32_t)h0 | ((uint32_t)h1 << 16);
    *(uint32_t*)(g_wimg_lo[img] + off) = (uint32_t)l0 | ((uint32_t)l1 << 16);
}

// ---------------------------------------------------------------------------
// CSR: fused decoupled-lookback scan (NB <= 148 blocks, all co-resident)
// ---------------------------------------------------------------------------
__device__ __forceinline__ int block_scan_excl_1024(int val, int& total) {
    __shared__ int wsum[32];
    int lane = threadIdx.x & 31, w = threadIdx.x >> 5;
    int inc = val;
#pragma unroll
    for (int o = 1; o < 32; o <<= 1) {
        int u = __shfl_up_sync(0xffffffffu, inc, o);
        if (lane >= o) inc += u;
    }
    if (lane == 31) wsum[w] = inc;
    __syncthreads();
    if (w == 0) {
        int v = wsum[lane];
#pragma unroll
        for (int o = 1; o < 32; o <<= 1) {
            int u = __shfl_up_sync(0xffffffffu, v, o);
            if (lane >= o) v += u;
        }
        wsum[lane] = v;
    }
    __syncthreads();
    int off = (w > 0) ? wsum[w - 1] : 0;
    total = wsum[31];
    return off + inc - val;
}

__global__ void k_scan(int N, int E) {
    int b = blockIdx.x, t = threadIdx.x;
    int idx = b * 1024 + t;
    int val = (idx < N) ? g_cnt[idx] : 0;
    int total;
    int ex = block_scan_excl_1024(val, total);
    if (t == 0) atomicExch(&g_bsum[b], total + 1);   // publish (sentinel +1)
    // lookback: thread t (< b) waits for block t's total
    int my = 0;
    if (t < b) {
        int v;
        do { v = atomicAdd(&g_bsum[t], 0); } while (v == 0);
        my = v - 1;
    }
    __shared__ int red[32];
    int lane = t & 31, w = t >> 5;
#pragma unroll
    for (int o = 16; o > 0; o >>= 1) my += __shfl_xor_sync(0xffffffffu, my, o);
    if (lane == 0) red[w] = my;
    __syncthreads();
    if (t == 0) {
        int s = 0;
#pragma unroll
        for (int i = 0; i < 32; i++) s += red[i];
        red[0] = s;
    }
    __syncthreads();
    int off = red[0];
    if (idx < N) {
        g_rowptr[idx] = ex + off;
        g_fill[idx]   = ex + off;
    }
    if (b == 0 && t == 0) g_rowptr[N] = E;
}

// Scatter: 4 edges per thread, vector loads, 4 independent atomic chains.
// Exposed ATOMG latency amortized 4x; kernel becomes L2-atomic-throughput bound.
__global__ void k_scatter(const int* __restrict__ ei, int E) {
    int i = (blockIdx.x * blockDim.x + threadIdx.x) * 4;
    if (i + 4 <= E) {
        int4 d = *(const int4*)&ei[E + i];
        int4 s = *(const int4*)&ei[i];
        int p0 = atomicAdd(&g_fill[d.x], 1);
        int p1 = atomicAdd(&g_fill[d.y], 1);
        int p2 = atomicAdd(&g_fill[d.z], 1);
        int p3 = atomicAdd(&g_fill[d.w], 1);
        g_adj[p0] = s.x;
        g_adj[p1] = s.y;
        g_adj[p2] = s.z;
        g_adj[p3] = s.w;
    } else {
        for (; i < E; i++) {
            int dd = ei[E + i];
            int p = atomicAdd(&g_fill[dd], 1);
            g_adj[p] = ei[i];
        }
    }
}

// ---------------------------------------------------------------------------
// HMMA GEMM (layers 1/2): Y[128x128] = X @ [Wl|Wr], 3-term bf16 split.
// PRE=false: convert fp32 X in-kernel, extra blocks run the edge histogram.
// PRE=true : A loaded from pre-split global bf16 hi/lo images (uint4 copy).
// Epilogue: cols<64 -> fp16 xl, cols>=64 -> fp32 xr.
// ---------------------------------------------------------------------------
#define SMA_HI 0
#define SMA_LO 16384
#define SMB_HI 32768
#define SMB_LO 49152
#define SM_TOT 65536

template <bool PRE>
__global__ void __launch_bounds__(256, 2) k_mma(const float* __restrict__ X,
                                                const unsigned char* __restrict__ Ahi,
                                                const unsigned char* __restrict__ Alo,
                                                const unsigned char* __restrict__ Bhi,
                                                const unsigned char* __restrict__ Blo,
                                                __half2* __restrict__ Y0h,
                                                float* __restrict__ Y1, int N,
                                                const int* __restrict__ ei, int E, int GB) {
    if (!PRE && blockIdx.x >= (unsigned)GB) {
        // histogram side-grid (independent of GEMM work)
        for (int i = (blockIdx.x - GB) * 256 + threadIdx.x; i < E; i += 1024 * 256)
            atomicAdd(&g_cnt[ei[E + i]], 1);
        return;
    }
    extern __shared__ char smem[];
    const uint32_t sb = smem_u32(smem);
    const int tid = threadIdx.x, wid = tid >> 5, lane = tid & 31;
    const int rowbase = blockIdx.x * 128;

    const uint4* bh = (const uint4*)Bhi;
    const uint4* bl = (const uint4*)Blo;
#pragma unroll
    for (int i = tid; i < 1024; i += 256) {
        ((uint4*)(smem + SMB_HI))[i] = bh[i];
        ((uint4*)(smem + SMB_LO))[i] = bl[i];
    }
    if (PRE) {
        const uint4* ah = (const uint4*)(Ahi + (size_t)rowbase * 128);
        const uint4* al = (const uint4*)(Alo + (size_t)rowbase * 128);
#pragma unroll
        for (int i = tid; i < 1024; i += 256) {
            ((uint4*)(smem + SMA_HI))[i] = ah[i];
            ((uint4*)(smem + SMA_LO))[i] = al[i];
        }
    } else {
#pragma unroll
        for (int i = tid; i < 4096; i += 256) {
            int r = i >> 5, kp = i & 31;
            int row = rowbase + r;
            float2 v = (row < N) ? *(const float2*)&X[row * 64 + 2 * kp]
                                 : make_float2(0.f, 0.f);
            uint16_t h0, l0, h1, l1;
            bf16_split(v.x, h0, l0);
            bf16_split(v.y, h1, l1);
            uint32_t off = swz_off(r, kp * 4);
            *(uint32_t*)(smem + SMA_HI + off) = (uint32_t)h0 | ((uint32_t)h1 << 16);
            *(uint32_t*)(smem + SMA_LO + off) = (uint32_t)l0 | ((uint32_t)l1 << 16);
        }
    }
    __syncthreads();

    const int m0 = (wid & 3) * 32;
    const int n0 = (wid >> 2) * 64;
    const int rl  = lane & 7;
    const int grp = lane >> 3;

    float acc[2][8][4];
#pragma unroll
    for (int mt = 0; mt < 2; mt++)
#pragma unroll
        for (int nt = 0; nt < 8; nt++)
#pragma unroll
            for (int j = 0; j < 4; j++) acc[mt][nt][j] = 0.f;

#pragma unroll
    for (int ks = 0; ks < 4; ks++) {
        const int cb = ks * 32;
        uint32_t ahi[2][4], alo[2][4];
#pragma unroll
        for (int mt = 0; mt < 2; mt++) {
            int arow = m0 + mt * 16 + (grp & 1) * 8 + rl;
            int abyte = cb + (grp >> 1) * 16;
            ldm_x4(ahi[mt], sb + SMA_HI + swz_off(arow, abyte));
            ldm_x4(alo[mt], sb + SMA_LO + swz_off(arow, abyte));
        }
#pragma unroll
        for (int np = 0; np < 4; np++) {
            int brow = n0 + np * 16 + (grp >> 1) * 8 + rl;
            int bbyte = cb + (grp & 1) * 16;
            uint32_t bhi[4], blo[4];
            ldm_x4(bhi, sb + SMB_HI + swz_off(brow, bbyte));
            ldm_x4(blo, sb + SMB_LO + swz_off(brow, bbyte));
            mma_bf16(acc[0][2 * np],     ahi[0], bhi[0], bhi[1]);
            mma_bf16(acc[1][2 * np],     ahi[1], bhi[0], bhi[1]);
            mma_bf16(acc[0][2 * np + 1], ahi[0], bhi[2], bhi[3]);
            mma_bf16(acc[1][2 * np + 1], ahi[1], bhi[2], bhi[3]);
            mma_bf16(acc[0][2 * np],     alo[0], bhi[0], bhi[1]);
            mma_bf16(acc[1][2 * np],     alo[1], bhi[0], bhi[1]);
            mma_bf16(acc[0][2 * np + 1], alo[0], bhi[2], bhi[3]);
            mma_bf16(acc[1][2 * np + 1], alo[1], bhi[2], bhi[3]);
            mma_bf16(acc[0][2 * np],     ahi[0], blo[0], blo[1]);
            mma_bf16(acc[1][2 * np],     ahi[1], blo[0], blo[1]);
            mma_bf16(acc[0][2 * np + 1], ahi[0], blo[2], blo[3]);
            mma_bf16(acc[1][2 * np + 1], ahi[1], blo[2], blo[3]);
        }
    }

    const int qr = lane >> 2, qc = (lane & 3) * 2;
#pragma unroll
    for (int mt = 0; mt < 2; mt++) {
#pragma unroll
        for (int nt = 0; nt < 8; nt++) {
            int col = n0 + nt * 8 + qc;
            int row0 = rowbase + m0 + mt * 16 + qr;
#pragma unroll
            for (int h = 0; h < 2; h++) {
                int row = row0 + h * 8;
                if (row < N) {
                    float vx = acc[mt][nt][2 * h], vy = acc[mt][nt][2 * h + 1];
                    if (col < 64) Y0h[row * 32 + (col >> 1)] = __floats2half2_rn(vx, vy);
                    else          *(float2*)&Y1[row * 64 + col - 64] = make_float2(vx, vy);
                }
            }
        }
    }
}

// ---------------------------------------------------------------------------
// Layer-3 fused GEMM: Y[128 x 256] = H @ [W3l | W3r], H from pre-split images.
// ---------------------------------------------------------------------------
#define SM3_AHI 0
#define SM3_ALO 16384
#define SM3_BHI 32768
#define SM3_BLO 65536
#define SM3_TOT 98304

__global__ void __launch_bounds__(512) k_mma3(const unsigned char* __restrict__ Ahi,
                                              const unsigned char* __restrict__ Alo,
                                              const unsigned char* __restrict__ Bhi2,
                                              const unsigned char* __restrict__ Blo2,
                                              const unsigned char* __restrict__ Bhi3,
                                              const unsigned char* __restrict__ Blo3,
                                              __half2* __restrict__ Y0h,
                                              float* __restrict__ Y1, int N) {
    extern __shared__ char smem[];
    const uint32_t sb = smem_u32(smem);
    const int tid = threadIdx.x, wid = tid >> 5, lane = tid & 31;
    const int rowbase = blockIdx.x * 128;

#pragma unroll
    for (int i = tid; i < 2048; i += 512) {
        ((uint4*)(smem + SM3_BHI))[i] = (i < 1024) ? ((const uint4*)Bhi2)[i]
                                                   : ((const uint4*)Bhi3)[i - 1024];
        ((uint4*)(smem + SM3_BLO))[i] = (i < 1024) ? ((const uint4*)Blo2)[i]
                                                   : ((const uint4*)Blo3)[i - 1024];
    }
    {
        const uint4* ah = (const uint4*)(Ahi + (size_t)rowbase * 128);
        const uint4* al = (const uint4*)(Alo + (size_t)rowbase * 128);
#pragma unroll
        for (int i = tid; i < 1024; i += 512) {
            ((uint4*)(smem + SM3_AHI))[i] = ah[i];
            ((uint4*)(smem + SM3_ALO))[i] = al[i];
        }
    }
    __syncthreads();

    const int m0 = (wid & 3) * 32;
    const int n0 = (wid >> 2) * 64;  // 0,64,128,192
    const int rl  = lane & 7;
    const int grp = lane >> 3;

    float acc[2][8][4];
#pragma unroll
    for (int mt = 0; mt < 2; mt++)
#pragma unroll
        for (int nt = 0; nt < 8; nt++)
#pragma unroll
            for (int j = 0; j < 4; j++) acc[mt][nt][j] = 0.f;

#pragma unroll
    for (int ks = 0; ks < 4; ks++) {
        const int cb = ks * 32;
        uint32_t ahi[2][4], alo[2][4];
#pragma unroll
        for (int mt = 0; mt < 2; mt++) {
            int arow = m0 + mt * 16 + (grp & 1) * 8 + rl;
            int abyte = cb + (grp >> 1) * 16;
            ldm_x4(ahi[mt], sb + SM3_AHI + swz_off(arow, abyte));
            ldm_x4(alo[mt], sb + SM3_ALO + swz_off(arow, abyte));
        }
#pragma unroll
        for (int np = 0; np < 4; np++) {
            int brow = n0 + np * 16 + (grp >> 1) * 8 + rl;
            int bbyte = cb + (grp & 1) * 16;
            uint32_t bhi[4], blo[4];
            ldm_x4(bhi, sb + SM3_BHI + swz_off(brow, bbyte));
            ldm_x4(blo, sb + SM3_BLO + swz_off(brow, bbyte));
            mma_bf16(acc[0][2 * np],     ahi[0], bhi[0], bhi[1]);
            mma_bf16(acc[1][2 * np],     ahi[1], bhi[0], bhi[1]);
            mma_bf16(acc[0][2 * np + 1], ahi[0], bhi[2], bhi[3]);
            mma_bf16(acc[1][2 * np + 1], ahi[1], bhi[2], bhi[3]);
            mma_bf16(acc[0][2 * np],     alo[0], bhi[0], bhi[1]);
            mma_bf16(acc[1][2 * np],     alo[1], bhi[0], bhi[1]);
            mma_bf16(acc[0][2 * np + 1], alo[0], bhi[2], bhi[3]);
            mma_bf16(acc[1][2 * np + 1], alo[1], bhi[2], bhi[3]);
            mma_bf16(acc[0][2 * np],     ahi[0], blo[0], blo[1]);
            mma_bf16(acc[1][2 * np],     ahi[1], blo[0], blo[1]);
            mma_bf16(acc[0][2 * np + 1], ahi[0], blo[2], blo[3]);
            mma_bf16(acc[1][2 * np + 1], ahi[1], blo[2], blo[3]);
        }
    }

    const int qr = lane >> 2, qc = (lane & 3) * 2;
#pragma unroll
    for (int mt = 0; mt < 2; mt++) {
#pragma unroll
        for (int nt = 0; nt < 8; nt++) {
            int col = n0 + nt * 8 + qc;
            int row0 = rowbase + m0 + mt * 16 + qr;
#pragma unroll
            for (int h = 0; h < 2; h++) {
                int row = row0 + h * 8;
                if (row < N) {
                    float vx = acc[mt][nt][2 * h], vy = acc[mt][nt][2 * h + 1];
                    if (col < 128) Y0h[row * 64 + (col >> 1)] = __floats2half2_rn(vx, vy);
                    else           *(float2*)&Y1[row * 128 + col - 128] = make_float2(vx, vy);
                }
            }
        }
    }
}

// ---------------------------------------------------------------------------
// Edge phase
// ---------------------------------------------------------------------------
__device__ __forceinline__ float leaky(float t) { return fmaxf(t, 0.2f * t); }

__device__ __forceinline__ float red8(float p) {
    p += __shfl_xor_sync(0xffffffffu, p, 4);
    p += __shfl_xor_sync(0xffffffffu, p, 2);
    p += __shfl_xor_sync(0xffffffffu, p, 1);
    return p;
}
__device__ __forceinline__ float red4(float p) {
    p += __shfl_xor_sync(0xffffffffu, p, 2);
    p += __shfl_xor_sync(0xffffffffu, p, 1);
    return p;
}
__device__ __forceinline__ float4 h2f4(uint2 u) {
    float2 lohalf = __half22float2(*(__half2*)&u.x);
    float2 hihalf = __half22float2(*(__half2*)&u.y);
    return make_float4(lohalf.x, lohalf.y, hihalf.x, hihalf.y);
}

// k_edge64: two nodes per warp (16 lanes each, 4 fp16 feats/lane), 4-edge
// pipeline, branchless lockstep, quad-merged online softmax. Output = ELU(..)
// written as pre-split bf16 hi/lo global images (swizzled GEMM layout).
__global__ void k_edge64(const __half2* __restrict__ XLH, const float* __restrict__ XR,
                         const float* __restrict__ att, const float* __restrict__ bias,
                         uint2* __restrict__ OHI, uint2* __restrict__ OLO, int N) {
    const int lane = threadIdx.x & 31;
    const int hl   = lane & 15;
    const int wg   = (blockIdx.x * blockDim.x + threadIdx.x) >> 5;
    const int n    = wg * 2 + (lane >> 4);
    const bool valid = n < N;
    const int nc = valid ? n : N - 1;

    const uint2* XL2 = (const uint2*)XLH;

    float4 a  = *(const float4*)&att[4 * hl];
    float4 xr = *(const float4*)&XR[nc * 64 + 4 * hl];
    float4 vs = h2f4(XL2[nc * 16 + hl]);

    auto score = [&](const float4& v) {
        return a.x * leaky(v.x + xr.x) + a.y * leaky(v.y + xr.y) +
               a.z * leaky(v.z + xr.z) + a.w * leaky(v.w + xr.w);
    };

    float m = red4(score(vs));
    float d = 1.f;
    float4 acc = vs;

    int beg = g_rowptr[nc];
    int end = valid ? g_rowptr[nc + 1] : beg;
    int cnt = end - beg;
    int ocnt = __shfl_xor_sync(0xffffffffu, cnt, 16);
    int nq = (max(cnt, ocnt) + 3) >> 2;

    int j = beg;
    int s0 = (j + 0 < end) ? g_adj[j + 0] : nc;
    int s1 = (j + 1 < end) ? g_adj[j + 1] : nc;
    int s2 = (j + 2 < end) ? g_adj[j + 2] : nc;
    int s3 = (j + 3 < end) ? g_adj[j + 3] : nc;

    for (int q = 0; q < nq; q++) {
        float4 v0 = h2f4(XL2[s0 * 16 + hl]);
        float4 v1 = h2f4(XL2[s1 * 16 + hl]);
        float4 v2 = h2f4(XL2[s2 * 16 + hl]);
        float4 v3 = h2f4(XL2[s3 * 16 + hl]);
        bool o0 = j + 0 < end, o1 = j + 1 < end, o2 = j + 2 < end, o3 = j + 3 < end;
        int jn = j + 4;
        s0 = (jn + 0 < end) ? g_adj[jn + 0] : nc;
        s1 = (jn + 1 < end) ? g_adj[jn + 1] : nc;
        s2 = (jn + 2 < end) ? g_adj[jn + 2] : nc;
        s3 = (jn + 3 < end) ? g_adj[jn + 3] : nc;
        j = jn;

        float p0 = red4(score(v0));
        float p1 = red4(score(v1));
        float p2 = red4(score(v2));
        float p3 = red4(score(v3));
        p0 = o0 ? p0 : -1e30f;
        p1 = o1 ? p1 : -1e30f;
        p2 = o2 ? p2 : -1e30f;
        p3 = o3 ? p3 : -1e30f;

        float mq = fmaxf(fmaxf(p0, p1), fmaxf(p2, p3));
        float mn = fmaxf(m, mq);
        float w  = __expf(m - mn);
        float e0 = __expf(p0 - mn), e1 = __expf(p1 - mn);
        float e2 = __expf(p2 - mn), e3 = __expf(p3 - mn);
        acc.x = acc.x * w + (e0 * v0.x + e1 * v1.x) + (e2 * v2.x + e3 * v3.x);
        acc.y = acc.y * w + (e0 * v0.y + e1 * v1.y) + (e2 * v2.y + e3 * v3.y);
        acc.z = acc.z * w + (e0 * v0.z + e1 * v1.z) + (e2 * v2.z + e3 * v3.z);
        acc.w = acc.w * w + (e0 * v0.w + e1 * v1.w) + (e2 * v2.w + e3 * v3.w);
        d = d * w + ((e0 + e1) + (e2 + e3));
        m = mn;
    }
    float inv = 1.f / d;
    float o0 = acc.x * inv + bias[4 * hl + 0];
    float o1 = acc.y * inv + bias[4 * hl + 1];
    float o2 = acc.z * inv + bias[4 * hl + 2];
    float o3 = acc.w * inv + bias[4 * hl + 3];
    o0 = o0 > 0.f ? o0 : (__expf(o0) - 1.f);
    o1 = o1 > 0.f ? o1 : (__expf(o1) - 1.f);
    o2 = o2 > 0.f ? o2 : (__expf(o2) - 1.f);
    o3 = o3 > 0.f ? o3 : (__expf(o3) - 1.f);
    if (valid) {
        uint16_t h0, l0, h1, l1, h2, l2, h3, l3;
        bf16_split(o0, h0, l0);
        bf16_split(o1, h1, l1);
        bf16_split(o2, h2, l2);
        bf16_split(o3, h3, l3);
        int idx = n * 16 + (hl ^ ((n & 7) << 1));   // swizzled 8B-unit offset
        OHI[idx] = make_uint2((uint32_t)h0 | ((uint32_t)h1 << 16),
                              (uint32_t)h2 | ((uint32_t)h3 << 16));
        OLO[idx] = make_uint2((uint32_t)l0 | ((uint32_t)l1 << 16),
                              (uint32_t)l2 | ((uint32_t)l3 << 16));
    }
}

__global__ void k_edge128_mean(const __half2* __restrict__ XLH, const float* __restrict__ XR,
                               const float* __restrict__ att, const float* __restrict__ bias,
                               float* __restrict__ OUT, int N) {
    int lane = threadIdx.x & 31;
    int n    = (blockIdx.x * blockDim.x + threadIdx.x) >> 5;
    if (n >= N) return;

    float4 a  = *(const float4*)&att[4 * lane];
    float4 xr = *(const float4*)&XR[n * 128 + 4 * lane];
    float4 vs = h2f4(*(const uint2*)&XLH[n * 64 + 2 * lane]);

    auto score = [&](const float4& v) {
        return a.x * leaky(v.x + xr.x) + a.y * leaky(v.y + xr.y) +
               a.z * leaky(v.z + xr.z) + a.w * leaky(v.w + xr.w);
    };

    float m = red8(score(vs));
    float d = 1.f;
    float4 acc = vs;

    int beg = g_rowptr[n], end = g_rowptr[n + 1];
    int i = beg;
    int s0 = 0, s1 = 0, s2 = 0, s3 = 0;
    if (i + 4 <= end) { s0 = g_adj[i]; s1 = g_adj[i+1]; s2 = g_adj[i+2]; s3 = g_adj[i+3]; }
    while (i + 4 <= end) {
        float4 v0 = h2f4(*(const uint2*)&XLH[s0 * 64 + 2 * lane]);
        float4 v1 = h2f4(*(const uint2*)&XLH[s1 * 64 + 2 * lane]);
        float4 v2 = h2f4(*(const uint2*)&XLH[s2 * 64 + 2 * lane]);
        float4 v3 = h2f4(*(const uint2*)&XLH[s3 * 64 + 2 * lane]);
        i += 4;
        if (i + 4 <= end) { s0 = g_adj[i]; s1 = g_adj[i+1]; s2 = g_adj[i+2]; s3 = g_adj[i+3]; }
        float p0 = score(v0), p1 = score(v1), p2 = score(v2), p3 = score(v3);
#pragma unroll
        for (int o = 4; o > 0; o >>= 1) {
            p0 += __shfl_xor_sync(0xffffffffu, p0, o);
            p1 += __shfl_xor_sync(0xffffffffu, p1, o);
            p2 += __shfl_xor_sync(0xffffffffu, p2, o);
            p3 += __shfl_xor_sync(0xffffffffu, p3, o);
        }
        float mq = fmaxf(fmaxf(p0, p1), fmaxf(p2, p3));
        float mn = fmaxf(m, mq);
        float w  = __expf(m - mn);
        float e0 = __expf(p0 - mn), e1 = __expf(p1 - mn);
        float e2 = __expf(p2 - mn), e3 = __expf(p3 - mn);
        acc.x = acc.x * w + (e0 * v0.x + e1 * v1.x) + (e2 * v2.x + e3 * v3.x);
        acc.y = acc.y * w + (e0 * v0.y + e1 * v1.y) + (e2 * v2.y + e3 * v3.y);
        acc.z = acc.z * w + (e0 * v0.z + e1 * v1.z) + (e2 * v2.z + e3 * v3.z);
        acc.w = acc.w * w + (e0 * v0.w + e1 * v1.w) + (e2 * v2.w + e3 * v3.w);
        d = d * w + ((e0 + e1) + (e2 + e3));
        m = mn;
    }
    for (; i < end; i++) {
        int s = g_adj[i];
        float4 v = h2f4(*(const uint2*)&XLH[s * 64 + 2 * lane]);
        float p = red8(score(v));
        float mn = fmaxf(m, p);
        float w  = __expf(m - mn);
        float e  = __expf(p - mn);
        acc.x = acc.x * w + e * v.x;
        acc.y = acc.y * w + e * v.y;
        acc.z = acc.z * w + e * v.z;
        acc.w = acc.w * w + e * v.w;
        d = d * w + e;
        m = mn;
    }
    float inv = 1.f / d;
    float o0 = acc.x * inv, o1 = acc.y * inv, o2 = acc.z * inv, o3 = acc.w * inv;
#pragma unroll
    for (int off = 8; off <= 16; off <<= 1) {
        o0 += __shfl_xor_sync(0xffffffffu, o0, off);
        o1 += __shfl_xor_sync(0xffffffffu, o1, off);
        o2 += __shfl_xor_sync(0xffffffffu, o2, off);
        o3 += __shfl_xor_sync(0xffffffffu, o3, off);
    }
    if (lane < 8) {
        int c = 4 * lane;
        float4 o = make_float4(0.25f * o0 + bias[c + 0],
                               0.25f * o1 + bias[c + 1],
                               0.25f * o2 + bias[c + 2],
                               0.25f * o3 + bias[c + 3]);
        *(float4*)&OUT[n * 32 + c] = o;
    }
}

// ---------------------------------------------------------------------------
// Launch (k_scatter at index 3 -> ncu capture target)
// ---------------------------------------------------------------------------
extern "C" void kernel_launch(void* const* d_in, const int* in_sizes, int n_in,
                              void* d_out, int out_size) {
    const float* x   = (const float*)d_in[0];
    const int*   ei  = (const int*)  d_in[1];
    const float* W1l = (const float*)d_in[2];
    const float* W1r = (const float*)d_in[3];
    const float* a1  = (const float*)d_in[4];
    const float* b1  = (const float*)d_in[5];
    const float* W2l = (const float*)d_in[6];
    const float* W2r = (const float*)d_in[7];
    const float* a2  = (const float*)d_in[8];
    const float* b2  = (const float*)d_in[9];
    const float* W3l = (const float*)d_in[10];
    const float* W3r = (const float*)d_in[11];
    const float* a3  = (const float*)d_in[12];
    const float* b3  = (const float*)d_in[13];
    float* out = (float*)d_out;

    const int N = in_sizes[0] / 64;
    const int E = in_sizes[1] / 2;
    const int NB = (N + 1023) / 1024;

    float *xlf, *xr;
    unsigned char *hhi, *hlo;
    unsigned char (*whi)[16384], (*wlo)[16384];
    cudaGetSymbolAddress((void**)&xlf, g_xl);
    cudaGetSymbolAddress((void**)&xr,  g_xr);
    cudaGetSymbolAddress((void**)&hhi, g_hhi);
    cudaGetSymbolAddress((void**)&hlo, g_hlo);
    cudaGetSymbolAddress((void**)&whi, g_wimg_hi);
    cudaGetSymbolAddress((void**)&wlo, g_wimg_lo);
    __half2* xlh = (__half2*)xlf;

    cudaFuncSetAttribute(k_mma<false>, cudaFuncAttributeMaxDynamicSharedMemorySize, SM_TOT);
    cudaFuncSetAttribute(k_mma<true>,  cudaFuncAttributeMaxDynamicSharedMemorySize, SM_TOT);
    cudaFuncSetAttribute(k_mma3, cudaFuncAttributeMaxDynamicSharedMemorySize, SM3_TOT);

    const int GT  = (N + 127) / 128;
    const int EB  = (N + 15) / 16;    // edge64: 8 warps x 2 nodes per block
    const int EBM = (N + 7) / 8;      // edge128: 8 warps x 1 node per block
    const int ZB  = (N + 255) / 256;
    const int SCB = (E / 4 + 255) / 256;  // scatter: 4 edges per thread

    // 0: init (zero cnt/bsum + W images)
    k_init<<<64 + ZB, 256>>>(W1l, W1r, W2l, W2r, W3l, W3r, N);
    // 1: layer-1 GEMM + histogram side-grid
    k_mma<false><<<GT + 1024, 256, SM_TOT>>>(x, nullptr, nullptr, whi[0], wlo[0],
                                             xlh, xr, N, ei, E, GT);
    // 2: fused decoupled-lookback scan
    k_scan<<<NB, 1024>>>(N, E);
    // 3: scatter, ILP-batched (ncu capture target)
    k_scatter<<<SCB, 256>>>(ei, E);
    // 4: layer-1 edge -> pre-split h images
    k_edge64<<<EB, 256>>>(xlh, xr, a1, b1, (uint2*)hhi, (uint2*)hlo, N);
    // 5: layer-2 GEMM (pre-split A)
    k_mma<true><<<GT, 256, SM_TOT>>>(nullptr, hhi, hlo, whi[1], wlo[1],
                                     xlh, xr, N, nullptr, 0, GT);
    // 6: layer-2 edge
    k_edge64<<<EB, 256>>>(xlh, xr, a2, b2, (uint2*)hhi, (uint2*)hlo, N);
    // 7: layer-3 fused dual-N GEMM (pre-split A)
    k_mma3<<<GT, 512, SM3_TOT>>>(hhi, hlo, whi[2], wlo[2], whi[3], wlo[3], xlh, xr, N);
    // 8: layer-3 edge (mean over heads) -> final output
    k_edge128_mean<<<EBM, 256>>>(xlh, xr, a3, b3, out, N);
}

// round 12
// speedup vs baseline: 1.4489x; 1.4489x over previous
#include <cuda_runtime.h>
#include <cuda_bf16.h>
#include <cuda_fp16.h>
#include <cstdint>

// Problem constants
#define NMAX 100000
#define EMAX 800000
#define HPAD 100096   // NMAX rounded up to 128 (tile padding)

// Scratch (no allocation allowed -> __device__ globals)
__device__ float g_xl[NMAX * 128];     // fp16 xl (half2) buffers
__device__ float g_xr[NMAX * 128];     // fp32 xr
__device__ __align__(16) unsigned char g_hhi[HPAD * 128];  // h bf16-hi image (swizzled)
__device__ __align__(16) unsigned char g_hlo[HPAD * 128];  // h bf16-lo image (swizzled)
__device__ int   g_cnt[NMAX];
__device__ int   g_rowptr[NMAX + 1];
__device__ int   g_fill[NMAX];
__device__ int   g_adj[EMAX];
__device__ int   g_bsum[128];
// bf16 [n=128][k=64] W images (XOR-swizzled): 0:[W1l|W1r] 1:[W2l|W2r] 2:W3l 3:W3r
__device__ __align__(16) unsigned char g_wimg_hi[4][16384];
__device__ __align__(16) unsigned char g_wimg_lo[4][16384];

// ---------------------------------------------------------------------------
// helpers
// ---------------------------------------------------------------------------
__device__ __forceinline__ uint32_t smem_u32(const void* p) {
    uint32_t a;
    asm("{ .reg .u64 t; cvta.to.shared.u64 t, %1; cvt.u32.u64 %0, t; }" : "=r"(a) : "l"(p));
    return a;
}
__device__ __forceinline__ void bf16_split(float v, uint16_t& hi, uint16_t& lo) {
    __nv_bfloat16 h = __float2bfloat16(v);
    float residual = v - __bfloat162float(h);
    __nv_bfloat16 l = __float2bfloat16(residual);
    hi = *(uint16_t*)&h;
    lo = *(uint16_t*)&l;
}
__device__ __forceinline__ void ldm_x4(uint32_t (&r)[4], uint32_t addr) {
    asm volatile("ldmatrix.sync.aligned.m8n8.x4.shared.b16 {%0,%1,%2,%3}, [%4];"
                 : "=r"(r[0]), "=r"(r[1]), "=r"(r[2]), "=r"(r[3]) : "r"(addr));
}
__device__ __forceinline__ void mma_bf16(float (&d)[4], const uint32_t (&a)[4],
                                         uint32_t b0, uint32_t b1) {
    asm volatile(
        "mma.sync.aligned.m16n8k16.row.col.f32.bf16.bf16.f32 "
        "{%0,%1,%2,%3}, {%4,%5,%6,%7}, {%8,%9}, {%0,%1,%2,%3};"
        : "+f"(d[0]), "+f"(d[1]), "+f"(d[2]), "+f"(d[3])
        : "r"(a[0]), "r"(a[1]), "r"(a[2]), "r"(a[3]), "r"(b0), "r"(b1));
}
// XOR swizzle inside a 128B row: 16B chunk index XORed with (row&7)
__device__ __forceinline__ uint32_t swz_off(int row, int byte_in_row) {
    return (uint32_t)(row * 128 + (byte_in_row ^ ((row & 7) << 4)));
}

// ---------------------------------------------------------------------------
// k_init: zero cnt + bsum, W -> bf16 hi/lo images
// ---------------------------------------------------------------------------
__global__ void k_init(const float* __restrict__ W1l, const float* __restrict__ W1r,
                       const float* __restrict__ W2l, const float* __restrict__ W2r,
                       const float* __restrict__ W3l, const float* __restrict__ W3r,
                       int N) {
    if (blockIdx.x >= 64) {
        int i = (blockIdx.x - 64) * 256 + threadIdx.x;
        if (i < N) g_cnt[i] = 0;
        if (blockIdx.x == 64 && threadIdx.x < 128) g_bsum[threadIdx.x] = 0;
        return;
    }
    int tid = blockIdx.x * 256 + threadIdx.x;   // 0..16383
    int img = tid >> 12, idx = tid & 4095;
    int n = idx >> 5, kp = idx & 31;
    int k0 = 2 * kp, k1 = k0 + 1;
    float v0, v1;
    if (img == 0) {
        v0 = (n < 64) ? W1l[k0 * 64 + n] : W1r[k0 * 64 + n - 64];
        v1 = (n < 64) ? W1l[k1 * 64 + n] : W1r[k1 * 64 + n - 64];
    } else if (img == 1) {
        v0 = (n < 64) ? W2l[k0 * 64 + n] : W2r[k0 * 64 + n - 64];
        v1 = (n < 64) ? W2l[k1 * 64 + n] : W2r[k1 * 64 + n - 64];
    } else if (img == 2) {
        v0 = W3l[k0 * 128 + n];
        v1 = W3l[k1 * 128 + n];
    } else {
        v0 = W3r[k0 * 128 + n];
        v1 = W3r[k1 * 128 + n];
    }
    uint16_t h0, l0, h1, l1;
    bf16_split(v0, h0, l0);
    bf16_split(v1, h1, l1);
    uint32_t off = swz_off(n, kp * 4);
    *(uint32_t*)(g_wimg_hi[img] + off) = (uint32_t)h0 | ((uint32_t)h1 << 16);
    *(uint32_t*)(g_wimg_lo[img] + off) = (uint32_t)l0 | ((uint32_t)l1 << 16);
}

// ---------------------------------------------------------------------------
// CSR: fused decoupled-lookback scan (NB <= 148 blocks, all co-resident)
// ---------------------------------------------------------------------------
__device__ __forceinline__ int block_scan_excl_1024(int val, int& total) {
    __shared__ int wsum[32];
    int lane = threadIdx.x & 31, w = threadIdx.x >> 5;
    int inc = val;
#pragma unroll
    for (int o = 1; o < 32; o <<= 1) {
        int u = __shfl_up_sync(0xffffffffu, inc, o);
        if (lane >= o) inc += u;
    }
    if (lane == 31) wsum[w] = inc;
    __syncthreads();
    if (w == 0) {
        int v = wsum[lane];
#pragma unroll
        for (int o = 1; o < 32; o <<= 1) {
            int u = __shfl_up_sync(0xffffffffu, v, o);
            if (lane >= o) v += u;
        }
        wsum[lane] = v;
    }
    __syncthreads();
    int off = (w > 0) ? wsum[w - 1] : 0;
    total = wsum[31];
    return off + inc - val;
}

__global__ void k_scan(int N, int E) {
    int b = blockIdx.x, t = threadIdx.x;
    int idx = b * 1024 + t;
    int val = (idx < N) ? g_cnt[idx] : 0;
    int total;
    int ex = block_scan_excl_1024(val, total);
    if (t == 0) atomicExch(&g_bsum[b], total + 1);   // publish (sentinel +1)
    // lookback: thread t (< b) waits for block t's total
    int my = 0;
    if (t < b) {
        int v;
        do { v = atomicAdd(&g_bsum[t], 0); } while (v == 0);
        my = v - 1;
    }
    __shared__ int red[32];
    int lane = t & 31, w = t >> 5;
#pragma unroll
    for (int o = 16; o > 0; o >>= 1) my += __shfl_xor_sync(0xffffffffu, my, o);
    if (lane == 0) red[w] = my;
    __syncthreads();
    if (t == 0) {
        int s = 0;
#pragma unroll
        for (int i = 0; i < 32; i++) s += red[i];
        red[0] = s;
    }
    __syncthreads();
    int off = red[0];
    if (idx < N) {
        g_rowptr[idx] = ex + off;
        g_fill[idx]   = ex + off;
    }
    if (b == 0 && t == 0) g_rowptr[N] = E;
}

__global__ void k_scatter(const int* __restrict__ ei, int E) {
    for (int i = blockIdx.x * blockDim.x + threadIdx.x; i < E; i += gridDim.x * blockDim.x) {
        int d = ei[E + i];
        int p = atomicAdd(&g_fill[d], 1);
        g_adj[p] = ei[i];
    }
}

// ---------------------------------------------------------------------------
// HMMA GEMM (layers 1/2): Y[128x128] = X @ [Wl|Wr], 3-term bf16 split.
// PRE=false: convert fp32 X in-kernel, extra blocks run the edge histogram.
// PRE=true : A loaded from pre-split global bf16 hi/lo images (uint4 copy).
// Epilogue: cols<64 -> fp16 xl, cols>=64 -> fp32 xr.
// ---------------------------------------------------------------------------
#define SMA_HI 0
#define SMA_LO 16384
#define SMB_HI 32768
#define SMB_LO 49152
#define SM_TOT 65536

template <bool PRE>
__global__ void __launch_bounds__(256, 2) k_mma(const float* __restrict__ X,
                                                const unsigned char* __restrict__ Ahi,
                                                const unsigned char* __restrict__ Alo,
                                                const unsigned char* __restrict__ Bhi,
                                                const unsigned char* __restrict__ Blo,
                                                __half2* __restrict__ Y0h,
                                                float* __restrict__ Y1, int N,
                                                const int* __restrict__ ei, int E, int GB) {
    if (!PRE && blockIdx.x >= (unsigned)GB) {
        // histogram side-grid (independent of GEMM work)
        for (int i = (blockIdx.x - GB) * 256 + threadIdx.x; i < E; i += 1024 * 256)
            atomicAdd(&g_cnt[ei[E + i]], 1);
        return;
    }
    extern __shared__ char smem[];
    const uint32_t sb = smem_u32(smem);
    const int tid = threadIdx.x, wid = tid >> 5, lane = tid & 31;
    const int rowbase = blockIdx.x * 128;

    const uint4* bh = (const uint4*)Bhi;
    const uint4* bl = (const uint4*)Blo;
#pragma unroll
    for (int i = tid; i < 1024; i += 256) {
        ((uint4*)(smem + SMB_HI))[i] = bh[i];
        ((uint4*)(smem + SMB_LO))[i] = bl[i];
    }
    if (PRE) {
        const uint4* ah = (const uint4*)(Ahi + (size_t)rowbase * 128);
        const uint4* al = (const uint4*)(Alo + (size_t)rowbase * 128);
#pragma unroll
        for (int i = tid; i < 1024; i += 256) {
            ((uint4*)(smem + SMA_HI))[i] = ah[i];
            ((uint4*)(smem + SMA_LO))[i] = al[i];
        }
    } else {
#pragma unroll
        for (int i = tid; i < 4096; i += 256) {
            int r = i >> 5, kp = i & 31;
            int row = rowbase + r;
            float2 v = (row < N) ? *(const float2*)&X[row * 64 + 2 * kp]
                                 : make_float2(0.f, 0.f);
            uint16_t h0, l0, h1, l1;
            bf16_split(v.x, h0, l0);
            bf16_split(v.y, h1, l1);
            uint32_t off = swz_off(r, kp * 4);
            *(uint32_t*)(smem + SMA_HI + off) = (uint32_t)h0 | ((uint32_t)h1 << 16);
            *(uint32_t*)(smem + SMA_LO + off) = (uint32_t)l0 | ((uint32_t)l1 << 16);
        }
    }
    __syncthreads();

    const int m0 = (wid & 3) * 32;
    const int n0 = (wid >> 2) * 64;
    const int rl  = lane & 7;
    const int grp = lane >> 3;

    float acc[2][8][4];
#pragma unroll
    for (int mt = 0; mt < 2; mt++)
#pragma unroll
        for (int nt = 0; nt < 8; nt++)
#pragma unroll
            for (int j = 0; j < 4; j++) acc[mt][nt][j] = 0.f;

#pragma unroll
    for (int ks = 0; ks < 4; ks++) {
        const int cb = ks * 32;
        uint32_t ahi[2][4], alo[2][4];
#pragma unroll
        for (int mt = 0; mt < 2; mt++) {
            int arow = m0 + mt * 16 + (grp & 1) * 8 + rl;
            int abyte = cb + (grp >> 1) * 16;
            ldm_x4(ahi[mt], sb + SMA_HI + swz_off(arow, abyte));
            ldm_x4(alo[mt], sb + SMA_LO + swz_off(arow, abyte));
        }
#pragma unroll
        for (int np = 0; np < 4; np++) {
            int brow = n0 + np * 16 + (grp >> 1) * 8 + rl;
            int bbyte = cb + (grp & 1) * 16;
            uint32_t bhi[4], blo[4];
            ldm_x4(bhi, sb + SMB_HI + swz_off(brow, bbyte));
            ldm_x4(blo, sb + SMB_LO + swz_off(brow, bbyte));
            mma_bf16(acc[0][2 * np],     ahi[0], bhi[0], bhi[1]);
            mma_bf16(acc[1][2 * np],     ahi[1], bhi[0], bhi[1]);
            mma_bf16(acc[0][2 * np + 1], ahi[0], bhi[2], bhi[3]);
            mma_bf16(acc[1][2 * np + 1], ahi[1], bhi[2], bhi[3]);
            mma_bf16(acc[0][2 * np],     alo[0], bhi[0], bhi[1]);
            mma_bf16(acc[1][2 * np],     alo[1], bhi[0], bhi[1]);
            mma_bf16(acc[0][2 * np + 1], alo[0], bhi[2], bhi[3]);
            mma_bf16(acc[1][2 * np + 1], alo[1], bhi[2], bhi[3]);
            mma_bf16(acc[0][2 * np],     ahi[0], blo[0], blo[1]);
            mma_bf16(acc[1][2 * np],     ahi[1], blo[0], blo[1]);
            mma_bf16(acc[0][2 * np + 1], ahi[0], blo[2], blo[3]);
            mma_bf16(acc[1][2 * np + 1], ahi[1], blo[2], blo[3]);
        }
    }

    const int qr = lane >> 2, qc = (lane & 3) * 2;
#pragma unroll
    for (int mt = 0; mt < 2; mt++) {
#pragma unroll
        for (int nt = 0; nt < 8; nt++) {
            int col = n0 + nt * 8 + qc;
            int row0 = rowbase + m0 + mt * 16 + qr;
#pragma unroll
            for (int h = 0; h < 2; h++) {
                int row = row0 + h * 8;
                if (row < N) {
                    float vx = acc[mt][nt][2 * h], vy = acc[mt][nt][2 * h + 1];
                    if (col < 64) Y0h[row * 32 + (col >> 1)] = __floats2half2_rn(vx, vy);
                    else          *(float2*)&Y1[row * 64 + col - 64] = make_float2(vx, vy);
                }
            }
        }
    }
}

// ---------------------------------------------------------------------------
// Layer-3 fused GEMM: Y[128 x 256] = H @ [W3l | W3r], H from pre-split images.
// ---------------------------------------------------------------------------
#define SM3_AHI 0
#define SM3_ALO 16384
#define SM3_BHI 32768
#define SM3_BLO 65536
#define SM3_TOT 98304

__global__ void __launch_bounds__(512) k_mma3(const unsigned char* __restrict__ Ahi,
                                              const unsigned char* __restrict__ Alo,
                                              const unsigned char* __restrict__ Bhi2,
                                              const unsigned char* __restrict__ Blo2,
                                              const unsigned char* __restrict__ Bhi3,
                                              const unsigned char* __restrict__ Blo3,
                                              __half2* __restrict__ Y0h,
                                              float* __restrict__ Y1, int N) {
    extern __shared__ char smem[];
    const uint32_t sb = smem_u32(smem);
    const int tid = threadIdx.x, wid = tid >> 5, lane = tid & 31;
    const int rowbase = blockIdx.x * 128;

#pragma unroll
    for (int i = tid; i < 2048; i += 512) {
        ((uint4*)(smem + SM3_BHI))[i] = (i < 1024) ? ((const uint4*)Bhi2)[i]
                                                   : ((const uint4*)Bhi3)[i - 1024];
        ((uint4*)(smem + SM3_BLO))[i] = (i < 1024) ? ((const uint4*)Blo2)[i]
                                                   : ((const uint4*)Blo3)[i - 1024];
    }
    {
        const uint4* ah = (const uint4*)(Ahi + (size_t)rowbase * 128);
        const uint4* al = (const uint4*)(Alo + (size_t)rowbase * 128);
#pragma unroll
        for (int i = tid; i < 1024; i += 512) {
            ((uint4*)(smem + SM3_AHI))[i] = ah[i];
            ((uint4*)(smem + SM3_ALO))[i] = al[i];
        }
    }
    __syncthreads();

    const int m0 = (wid & 3) * 32;
    const int n0 = (wid >> 2) * 64;  // 0,64,128,192
    const int rl  = lane & 7;
    const int grp = lane >> 3;

    float acc[2][8][4];
#pragma unroll
    for (int mt = 0; mt < 2; mt++)
#pragma unroll
        for (int nt = 0; nt < 8; nt++)
#pragma unroll
            for (int j = 0; j < 4; j++) acc[mt][nt][j] = 0.f;

#pragma unroll
    for (int ks = 0; ks < 4; ks++) {
        const int cb = ks * 32;
        uint32_t ahi[2][4], alo[2][4];
#pragma unroll
        for (int mt = 0; mt < 2; mt++) {
            int arow = m0 + mt * 16 + (grp & 1) * 8 + rl;
            int abyte = cb + (grp >> 1) * 16;
            ldm_x4(ahi[mt], sb + SM3_AHI + swz_off(arow, abyte));
            ldm_x4(alo[mt], sb + SM3_ALO + swz_off(arow, abyte));
        }
#pragma unroll
        for (int np = 0; np < 4; np++) {
            int brow = n0 + np * 16 + (grp >> 1) * 8 + rl;
            int bbyte = cb + (grp & 1) * 16;
            uint32_t bhi[4], blo[4];
            ldm_x4(bhi, sb + SM3_BHI + swz_off(brow, bbyte));
            ldm_x4(blo, sb + SM3_BLO + swz_off(brow, bbyte));
            mma_bf16(acc[0][2 * np],     ahi[0], bhi[0], bhi[1]);
            mma_bf16(acc[1][2 * np],     ahi[1], bhi[0], bhi[1]);
            mma_bf16(acc[0][2 * np + 1], ahi[0], bhi[2], bhi[3]);
            mma_bf16(acc[1][2 * np + 1], ahi[1], bhi[2], bhi[3]);
            mma_bf16(acc[0][2 * np],     alo[0], bhi[0], bhi[1]);
            mma_bf16(acc[1][2 * np],     alo[1], bhi[0], bhi[1]);
            mma_bf16(acc[0][2 * np + 1], alo[0], bhi[2], bhi[3]);
            mma_bf16(acc[1][2 * np + 1], alo[1], bhi[2], bhi[3]);
            mma_bf16(acc[0][2 * np],     ahi[0], blo[0], blo[1]);
            mma_bf16(acc[1][2 * np],     ahi[1], blo[0], blo[1]);
            mma_bf16(acc[0][2 * np + 1], ahi[0], blo[2], blo[3]);
            mma_bf16(acc[1][2 * np + 1], ahi[1], blo[2], blo[3]);
        }
    }

    const int qr = lane >> 2, qc = (lane & 3) * 2;
#pragma unroll
    for (int mt = 0; mt < 2; mt++) {
#pragma unroll
        for (int nt = 0; nt < 8; nt++) {
            int col = n0 + nt * 8 + qc;
            int row0 = rowbase + m0 + mt * 16 + qr;
#pragma unroll
            for (int h = 0; h < 2; h++) {
                int row = row0 + h * 8;
                if (row < N) {
                    float vx = acc[mt][nt][2 * h], vy = acc[mt][nt][2 * h + 1];
                    if (col < 128) Y0h[row * 64 + (col >> 1)] = __floats2half2_rn(vx, vy);
                    else           *(float2*)&Y1[row * 128 + col - 128] = make_float2(vx, vy);
                }
            }
        }
    }
}

// ---------------------------------------------------------------------------
// Edge phase
// ---------------------------------------------------------------------------
__device__ __forceinline__ float leaky(float t) { return fmaxf(t, 0.2f * t); }

__device__ __forceinline__ float red8(float p) {
    p += __shfl_xor_sync(0xffffffffu, p, 4);
    p += __shfl_xor_sync(0xffffffffu, p, 2);
    p += __shfl_xor_sync(0xffffffffu, p, 1);
    return p;
}
__device__ __forceinline__ float red4(float p) {
    p += __shfl_xor_sync(0xffffffffu, p, 2);
    p += __shfl_xor_sync(0xffffffffu, p, 1);
    return p;
}
__device__ __forceinline__ float4 h2f4(uint2 u) {
    float2 lohalf = __half22float2(*(__half2*)&u.x);
    float2 hihalf = __half22float2(*(__half2*)&u.y);
    return make_float4(lohalf.x, lohalf.y, hihalf.x, hihalf.y);
}

// k_edge64: two nodes per warp (16 lanes each, 4 fp16 feats/lane), 4-edge
// pipeline, branchless lockstep, quad-merged online softmax. Output = ELU(..)
// written as pre-split bf16 hi/lo global images (swizzled GEMM layout).
__global__ void k_edge64(const __half2* __restrict__ XLH, const float* __restrict__ XR,
                         const float* __restrict__ att, const float* __restrict__ bias,
                         uint2* __restrict__ OHI, uint2* __restrict__ OLO, int N) {
    const int lane = threadIdx.x & 31;
    const int hl   = lane & 15;
    const int wg   = (blockIdx.x * blockDim.x + threadIdx.x) >> 5;
    const int n    = wg * 2 + (lane >> 4);
    const bool valid = n < N;
    const int nc = valid ? n : N - 1;

    const uint2* XL2 = (const uint2*)XLH;

    float4 a  = *(const float4*)&att[4 * hl];
    float4 xr = *(const float4*)&XR[nc * 64 + 4 * hl];
    float4 vs = h2f4(XL2[nc * 16 + hl]);

    auto score = [&](const float4& v) {
        return a.x * leaky(v.x + xr.x) + a.y * leaky(v.y + xr.y) +
               a.z * leaky(v.z + xr.z) + a.w * leaky(v.w + xr.w);
    };

    float m = red4(score(vs));
    float d = 1.f;
    float4 acc = vs;

    int beg = g_rowptr[nc];
    int end = valid ? g_rowptr[nc + 1] : beg;
    int cnt = end - beg;
    int ocnt = __shfl_xor_sync(0xffffffffu, cnt, 16);
    int nq = (max(cnt, ocnt) + 3) >> 2;

    int j = beg;
    int s0 = (j + 0 < end) ? g_adj[j + 0] : nc;
    int s1 = (j + 1 < end) ? g_adj[j + 1] : nc;
    int s2 = (j + 2 < end) ? g_adj[j + 2] : nc;
    int s3 = (j + 3 < end) ? g_adj[j + 3] : nc;

    for (int q = 0; q < nq; q++) {
        float4 v0 = h2f4(XL2[s0 * 16 + hl]);
        float4 v1 = h2f4(XL2[s1 * 16 + hl]);
        float4 v2 = h2f4(XL2[s2 * 16 + hl]);
        float4 v3 = h2f4(XL2[s3 * 16 + hl]);
        bool o0 = j + 0 < end, o1 = j + 1 < end, o2 = j + 2 < end, o3 = j + 3 < end;
        int jn = j + 4;
        s0 = (jn + 0 < end) ? g_adj[jn + 0] : nc;
        s1 = (jn + 1 < end) ? g_adj[jn + 1] : nc;
        s2 = (jn + 2 < end) ? g_adj[jn + 2] : nc;
        s3 = (jn + 3 < end) ? g_adj[jn + 3] : nc;
        j = jn;

        float p0 = red4(score(v0));
        float p1 = red4(score(v1));
        float p2 = red4(score(v2));
        float p3 = red4(score(v3));
        p0 = o0 ? p0 : -1e30f;
        p1 = o1 ? p1 : -1e30f;
        p2 = o2 ? p2 : -1e30f;
        p3 = o3 ? p3 : -1e30f;

        float mq = fmaxf(fmaxf(p0, p1), fmaxf(p2, p3));
        float mn = fmaxf(m, mq);
        float w  = __expf(m - mn);
        float e0 = __expf(p0 - mn), e1 = __expf(p1 - mn);
        float e2 = __expf(p2 - mn), e3 = __expf(p3 - mn);
        acc.x = acc.x * w + (e0 * v0.x + e1 * v1.x) + (e2 * v2.x + e3 * v3.x);
        acc.y = acc.y * w + (e0 * v0.y + e1 * v1.y) + (e2 * v2.y + e3 * v3.y);
        acc.z = acc.z * w + (e0 * v0.z + e1 * v1.z) + (e2 * v2.z + e3 * v3.z);
        acc.w = acc.w * w + (e0 * v0.w + e1 * v1.w) + (e2 * v2.w + e3 * v3.w);
        d = d * w + ((e0 + e1) + (e2 + e3));
        m = mn;
    }
    float inv = 1.f / d;
    float o0 = acc.x * inv + bias[4 * hl + 0];
    float o1 = acc.y * inv + bias[4 * hl + 1];
    float o2 = acc.z * inv + bias[4 * hl + 2];
    float o3 = acc.w * inv + bias[4 * hl + 3];
    o0 = o0 > 0.f ? o0 : (__expf(o0) - 1.f);
    o1 = o1 > 0.f ? o1 : (__expf(o1) - 1.f);
    o2 = o2 > 0.f ? o2 : (__expf(o2) - 1.f);
    o3 = o3 > 0.f ? o3 : (__expf(o3) - 1.f);
    if (valid) {
        uint16_t h0, l0, h1, l1, h2, l2, h3, l3;
        bf16_split(o0, h0, l0);
        bf16_split(o1, h1, l1);
        bf16_split(o2, h2, l2);
        bf16_split(o3, h3, l3);
        int idx = n * 16 + (hl ^ ((n & 7) << 1));   // swizzled 8B-unit offset
        OHI[idx] = make_uint2((uint32_t)h0 | ((uint32_t)h1 << 16),
                              (uint32_t)h2 | ((uint32_t)h3 << 16));
        OLO[idx] = make_uint2((uint32_t)l0 | ((uint32_t)l1 << 16),
                              (uint32_t)l2 | ((uint32_t)l3 << 16));
    }
}

__global__ void k_edge128_mean(const __half2* __restrict__ XLH, const float* __restrict__ XR,
                               const float* __restrict__ att, const float* __restrict__ bias,
                               float* __restrict__ OUT, int N) {
    int lane = threadIdx.x & 31;
    int n    = (blockIdx.x * blockDim.x + threadIdx.x) >> 5;
    if (n >= N) return;

    float4 a  = *(const float4*)&att[4 * lane];
    float4 xr = *(const float4*)&XR[n * 128 + 4 * lane];
    float4 vs = h2f4(*(const uint2*)&XLH[n * 64 + 2 * lane]);

    auto score = [&](const float4& v) {
        return a.x * leaky(v.x + xr.x) + a.y * leaky(v.y + xr.y) +
               a.z * leaky(v.z + xr.z) + a.w * leaky(v.w + xr.w);
    };

    float m = red8(score(vs));
    float d = 1.f;
    float4 acc = vs;

    int beg = g_rowptr[n], end = g_rowptr[n + 1];
    int i = beg;
    int s0 = 0, s1 = 0, s2 = 0, s3 = 0;
    if (i + 4 <= end) { s0 = g_adj[i]; s1 = g_adj[i+1]; s2 = g_adj[i+2]; s3 = g_adj[i+3]; }
    while (i + 4 <= end) {
        float4 v0 = h2f4(*(const uint2*)&XLH[s0 * 64 + 2 * lane]);
        float4 v1 = h2f4(*(const uint2*)&XLH[s1 * 64 + 2 * lane]);
        float4 v2 = h2f4(*(const uint2*)&XLH[s2 * 64 + 2 * lane]);
        float4 v3 = h2f4(*(const uint2*)&XLH[s3 * 64 + 2 * lane]);
        i += 4;
        if (i + 4 <= end) { s0 = g_adj[i]; s1 = g_adj[i+1]; s2 = g_adj[i+2]; s3 = g_adj[i+3]; }
        float p0 = score(v0), p1 = score(v1), p2 = score(v2), p3 = score(v3);
#pragma unroll
        for (int o = 4; o > 0; o >>= 1) {
            p0 += __shfl_xor_sync(0xffffffffu, p0, o);
            p1 += __shfl_xor_sync(0xffffffffu, p1, o);
            p2 += __shfl_xor_sync(0xffffffffu, p2, o);
            p3 += __shfl_xor_sync(0xffffffffu, p3, o);
        }
        float mq = fmaxf(fmaxf(p0, p1), fmaxf(p2, p3));
        float mn = fmaxf(m, mq);
        float w  = __expf(m - mn);
        float e0 = __expf(p0 - mn), e1 = __expf(p1 - mn);
        float e2 = __expf(p2 - mn), e3 = __expf(p3 - mn);
        acc.x = acc.x * w + (e0 * v0.x + e1 * v1.x) + (e2 * v2.x + e3 * v3.x);
        acc.y = acc.y * w + (e0 * v0.y + e1 * v1.y) + (e2 * v2.y + e3 * v3.y);
        acc.z = acc.z * w + (e0 * v0.z + e1 * v1.z) + (e2 * v2.z + e3 * v3.z);
        acc.w = acc.w * w + (e0 * v0.w + e1 * v1.w) + (e2 * v2.w + e3 * v3.w);
        d = d * w + ((e0 + e1) + (e2 + e3));
        m = mn;
    }
    for (; i < end; i++) {
        int s = g_adj[i];
        float4 v = h2f4(*(const uint2*)&XLH[s * 64 + 2 * lane]);
        float p = red8(score(v));
        float mn = fmaxf(m, p);
        float w  = __expf(m - mn);
        float e  = __expf(p - mn);
        acc.x = acc.x * w + e * v.x;
        acc.y = acc.y * w + e * v.y;
        acc.z = acc.z * w + e * v.z;
        acc.w = acc.w * w + e * v.w;
        d = d * w + e;
        m = mn;
    }
    float inv = 1.f / d;
    float o0 = acc.x * inv, o1 = acc.y * inv, o2 = acc.z * inv, o3 = acc.w * inv;
#pragma unroll
    for (int off = 8; off <= 16; off <<= 1) {
        o0 += __shfl_xor_sync(0xffffffffu, o0, off);
        o1 += __shfl_xor_sync(0xffffffffu, o1, off);
        o2 += __shfl_xor_sync(0xffffffffu, o2, off);
        o3 += __shfl_xor_sync(0xffffffffu, o3, off);
    }
    if (lane < 8) {
        int c = 4 * lane;
        float4 o = make_float4(0.25f * o0 + bias[c + 0],
                               0.25f * o1 + bias[c + 1],
                               0.25f * o2 + bias[c + 2],
                               0.25f * o3 + bias[c + 3]);
        *(float4*)&OUT[n * 32 + c] = o;
    }
}

// ---------------------------------------------------------------------------
// Launch (k_scatter at index 3 -> ncu capture target)
// ---------------------------------------------------------------------------
extern "C" void kernel_launch(void* const* d_in, const int* in_sizes, int n_in,
                              void* d_out, int out_size) {
    const float* x   = (const float*)d_in[0];
    const int*   ei  = (const int*)  d_in[1];
    const float* W1l = (const float*)d_in[2];
    const float* W1r = (const float*)d_in[3];
    const float* a1  = (const float*)d_in[4];
    const float* b1  = (const float*)d_in[5];
    const float* W2l = (const float*)d_in[6];
    const float* W2r = (const float*)d_in[7];
    const float* a2  = (const float*)d_in[8];
    const float* b2  = (const float*)d_in[9];
    const float* W3l = (const float*)d_in[10];
    const float* W3r = (const float*)d_in[11];
    const float* a3  = (const float*)d_in[12];
    const float* b3  = (const float*)d_in[13];
    float* out = (float*)d_out;

    const int N = in_sizes[0] / 64;
    const int E = in_sizes[1] / 2;
    const int NB = (N + 1023) / 1024;

    float *xlf, *xr;
    unsigned char *hhi, *hlo;
    unsigned char (*whi)[16384], (*wlo)[16384];
    cudaGetSymbolAddress((void**)&xlf, g_xl);
    cudaGetSymbolAddress((void**)&xr,  g_xr);
    cudaGetSymbolAddress((void**)&hhi, g_hhi);
    cudaGetSymbolAddress((void**)&hlo, g_hlo);
    cudaGetSymbolAddress((void**)&whi, g_wimg_hi);
    cudaGetSymbolAddress((void**)&wlo, g_wimg_lo);
    __half2* xlh = (__half2*)xlf;

    cudaFuncSetAttribute(k_mma<false>, cudaFuncAttributeMaxDynamicSharedMemorySize, SM_TOT);
    cudaFuncSetAttribute(k_mma<true>,  cudaFuncAttributeMaxDynamicSharedMemorySize, SM_TOT);
    cudaFuncSetAttribute(k_mma3, cudaFuncAttributeMaxDynamicSharedMemorySize, SM3_TOT);

    const int GT  = (N + 127) / 128;
    const int EB  = (N + 15) / 16;    // edge64: 8 warps x 2 nodes per block
    const int EBM = (N + 7) / 8;      // edge128: 8 warps x 1 node per block
    const int ZB  = (N + 255) / 256;

    // 0: init (zero cnt/bsum + W images)
    k_init<<<64 + ZB, 256>>>(W1l, W1r, W2l, W2r, W3l, W3r, N);
    // 1: layer-1 GEMM + histogram side-grid
    k_mma<false><<<GT + 1024, 256, SM_TOT>>>(x, nullptr, nullptr, whi[0], wlo[0],
                                             xlh, xr, N, ei, E, GT);
    // 2: fused decoupled-lookback scan
    k_scan<<<NB, 1024>>>(N, E);
    // 3: scatter (ncu capture target)
    k_scatter<<<1024, 256>>>(ei, E);
    // 4: layer-1 edge -> pre-split h images
    k_edge64<<<EB, 256>>>(xlh, xr, a1, b1, (uint2*)hhi, (uint2*)hlo, N);
    // 5: layer-2 GEMM (pre-split A)
    k_mma<true><<<GT, 256, SM_TOT>>>(nullptr, hhi, hlo, whi[1], wlo[1],
                                     xlh, xr, N, nullptr, 0, GT);
    // 6: layer-2 edge
    k_edge64<<<EB, 256>>>(xlh, xr, a2, b2, (uint2*)hhi, (uint2*)hlo, N);
    // 7: layer-3 fused dual-N GEMM (pre-split A)
    k_mma3<<<GT, 512, SM3_TOT>>>(hhi, hlo, whi[2], wlo[2], whi[3], wlo[3], xlh, xr, N);
    // 8: layer-3 edge (mean over heads) -> final output
    k_edge128_mean<<<EBM, 256>>>(xlh, xr, a3, b3, out, N);
}

// round 13
// speedup vs baseline: 1.5052x; 1.0388x over previous
#include <cuda_runtime.h>
#include <cuda_bf16.h>
#include <cuda_fp16.h>
#include <cstdint>

// Problem constants
#define NMAX 100000
#define EMAX 800000
#define HPAD 100096   // NMAX rounded up to 128 (tile padding)

// Scratch (no allocation allowed -> __device__ globals)
// NOTE: g_cnt/g_bsum rely on zero-at-entry: zero at module load, re-zeroed by
// k_scan (g_cnt) and k_hist (g_bsum) on every call -> invariant holds per replay.
__device__ float g_xl[NMAX * 128];     // fp16 xl (half2) buffers
__device__ float g_xr[NMAX * 128];     // fp32 xr
__device__ __align__(16) unsigned char g_hhi[HPAD * 128];  // h bf16-hi image (swizzled)
__device__ __align__(16) unsigned char g_hlo[HPAD * 128];  // h bf16-lo image (swizzled)
__device__ int   g_cnt[NMAX];
__device__ int   g_rowptr[NMAX + 1];
__device__ int   g_fill[NMAX];
__device__ int   g_adj[EMAX];
__device__ int   g_bsum[128];
// bf16 [n=128][k=64] W images (XOR-swizzled): 0:[W1l|W1r] 1:[W2l|W2r] 2:W3l 3:W3r
__device__ __align__(16) unsigned char g_wimg_hi[4][16384];
__device__ __align__(16) unsigned char g_wimg_lo[4][16384];

// ---------------------------------------------------------------------------
// helpers
// ---------------------------------------------------------------------------
__device__ __forceinline__ uint32_t smem_u32(const void* p) {
    uint32_t a;
    asm("{ .reg .u64 t; cvta.to.shared.u64 t, %1; cvt.u32.u64 %0, t; }" : "=r"(a) : "l"(p));
    return a;
}
__device__ __forceinline__ void bf16_split(float v, uint16_t& hi, uint16_t& lo) {
    __nv_bfloat16 h = __float2bfloat16(v);
    float residual = v - __bfloat162float(h);
    __nv_bfloat16 l = __float2bfloat16(residual);
    hi = *(uint16_t*)&h;
    lo = *(uint16_t*)&l;
}
__device__ __forceinline__ void ldm_x4(uint32_t (&r)[4], uint32_t addr) {
    asm volatile("ldmatrix.sync.aligned.m8n8.x4.shared.b16 {%0,%1,%2,%3}, [%4];"
                 : "=r"(r[0]), "=r"(r[1]), "=r"(r[2]), "=r"(r[3]) : "r"(addr));
}
__device__ __forceinline__ void mma_bf16(float (&d)[4], const uint32_t (&a)[4],
                                         uint32_t b0, uint32_t b1) {
    asm volatile(
        "mma.sync.aligned.m16n8k16.row.col.f32.bf16.bf16.f32 "
        "{%0,%1,%2,%3}, {%4,%5,%6,%7}, {%8,%9}, {%0,%1,%2,%3};"
        : "+f"(d[0]), "+f"(d[1]), "+f"(d[2]), "+f"(d[3])
        : "r"(a[0]), "r"(a[1]), "r"(a[2]), "r"(a[3]), "r"(b0), "r"(b1));
}
// XOR swizzle inside a 128B row: 16B chunk index XORed with (row&7)
__device__ __forceinline__ uint32_t swz_off(int row, int byte_in_row) {
    return (uint32_t)(row * 128 + (byte_in_row ^ ((row & 7) << 4)));
}

// ---------------------------------------------------------------------------
// k_hist: blocks 0-63 build W bf16 hi/lo images; blocks 64+ run the edge
// histogram (g_cnt zero-at-entry, re-zeroed by k_scan); block 64 zeroes bsum.
// ---------------------------------------------------------------------------
__global__ void k_hist(const int* __restrict__ ei, int E,
                       const float* __restrict__ W1l, const float* __restrict__ W1r,
                       const float* __restrict__ W2l, const float* __restrict__ W2r,
                       const float* __restrict__ W3l, const float* __restrict__ W3r) {
    if (blockIdx.x >= 64) {
        if (blockIdx.x == 64 && threadIdx.x < 128) g_bsum[threadIdx.x] = 0;
        for (int i = (blockIdx.x - 64) * 256 + threadIdx.x; i < E; i += 1024 * 256)
            atomicAdd(&g_cnt[ei[E + i]], 1);
        return;
    }
    int tid = blockIdx.x * 256 + threadIdx.x;   // 0..16383
    int img = tid >> 12, idx = tid & 4095;
    int n = idx >> 5, kp = idx & 31;
    int k0 = 2 * kp, k1 = k0 + 1;
    float v0, v1;
    if (img == 0) {
        v0 = (n < 64) ? W1l[k0 * 64 + n] : W1r[k0 * 64 + n - 64];
        v1 = (n < 64) ? W1l[k1 * 64 + n] : W1r[k1 * 64 + n - 64];
    } else if (img == 1) {
        v0 = (n < 64) ? W2l[k0 * 64 + n] : W2r[k0 * 64 + n - 64];
        v1 = (n < 64) ? W2l[k1 * 64 + n] : W2r[k1 * 64 + n - 64];
    } else if (img == 2) {
        v0 = W3l[k0 * 128 + n];
        v1 = W3l[k1 * 128 + n];
    } else {
        v0 = W3r[k0 * 128 + n];
        v1 = W3r[k1 * 128 + n];
    }
    uint16_t h0, l0, h1, l1;
    bf16_split(v0, h0, l0);
    bf16_split(v1, h1, l1);
    uint32_t off = swz_off(n, kp * 4);
    *(uint32_t*)(g_wimg_hi[img] + off) = (uint32_t)h0 | ((uint32_t)h1 << 16);
    *(uint32_t*)(g_wimg_lo[img] + off) = (uint32_t)l0 | ((uint32_t)l1 << 16);
}

// ---------------------------------------------------------------------------
// CSR: fused decoupled-lookback scan (NB <= 148 blocks, all co-resident).
// Also re-zeroes g_cnt for the next replay.
// ---------------------------------------------------------------------------
__device__ __forceinline__ int block_scan_excl_1024(int val, int& total) {
    __shared__ int wsum[32];
    int lane = threadIdx.x & 31, w = threadIdx.x >> 5;
    int inc = val;
#pragma unroll
    for (int o = 1; o < 32; o <<= 1) {
        int u = __shfl_up_sync(0xffffffffu, inc, o);
        if (lane >= o) inc += u;
    }
    if (lane == 31) wsum[w] = inc;
    __syncthreads();
    if (w == 0) {
        int v = wsum[lane];
#pragma unroll
        for (int o = 1; o < 32; o <<= 1) {
            int u = __shfl_up_sync(0xffffffffu, v, o);
            if (lane >= o) v += u;
        }
        wsum[lane] = v;
    }
    __syncthreads();
    int off = (w > 0) ? wsum[w - 1] : 0;
    total = wsum[31];
    return off + inc - val;
}

__global__ void k_scan(int N, int E) {
    int b = blockIdx.x, t = threadIdx.x;
    int idx = b * 1024 + t;
    int val = (idx < N) ? g_cnt[idx] : 0;
    if (idx < N) g_cnt[idx] = 0;                 // re-zero for next replay
    int total;
    int ex = block_scan_excl_1024(val, total);
    if (t == 0) atomicExch(&g_bsum[b], total + 1);   // publish (sentinel +1)
    // lookback: thread t (< b) waits for block t's total
    int my = 0;
    if (t < b) {
        int v;
        do { v = atomicAdd(&g_bsum[t], 0); } while (v == 0);
        my = v - 1;
    }
    __shared__ int red[32];
    int lane = t & 31, w = t >> 5;
#pragma unroll
    for (int o = 16; o > 0; o >>= 1) my += __shfl_xor_sync(0xffffffffu, my, o);
    if (lane == 0) red[w] = my;
    __syncthreads();
    if (t == 0) {
        int s = 0;
#pragma unroll
        for (int i = 0; i < 32; i++) s += red[i];
        red[0] = s;
    }
    __syncthreads();
    int off = red[0];
    if (idx < N) {
        g_rowptr[idx] = ex + off;
        g_fill[idx]   = ex + off;
    }
    if (b == 0 && t == 0) g_rowptr[N] = E;
}

// ---------------------------------------------------------------------------
// HMMA GEMM (layers 1/2): Y[128x128] = X @ [Wl|Wr], 3-term bf16 split.
// PRE=false: convert fp32 X in-kernel; extra blocks run the CSR SCATTER
//            (hidden under the GEMM; loop identical to the proven R12 scatter).
// PRE=true : A loaded from pre-split global bf16 hi/lo images (uint4 copy).
// Epilogue: cols<64 -> fp16 xl, cols>=64 -> fp32 xr.
// ---------------------------------------------------------------------------
#define SMA_HI 0
#define SMA_LO 16384
#define SMB_HI 32768
#define SMB_LO 49152
#define SM_TOT 65536

template <bool PRE>
__global__ void __launch_bounds__(256, 2) k_mma(const float* __restrict__ X,
                                                const unsigned char* __restrict__ Ahi,
                                                const unsigned char* __restrict__ Alo,
                                                const unsigned char* __restrict__ Bhi,
                                                const unsigned char* __restrict__ Blo,
                                                __half2* __restrict__ Y0h,
                                                float* __restrict__ Y1, int N,
                                                const int* __restrict__ ei, int E, int GB) {
    if (!PRE && blockIdx.x >= (unsigned)GB) {
        // scatter side-grid (needs rowptr from k_scan; independent of GEMM)
        for (int i = (blockIdx.x - GB) * 256 + threadIdx.x; i < E; i += 1024 * 256) {
            int d = ei[E + i];
            int p = atomicAdd(&g_fill[d], 1);
            g_adj[p] = ei[i];
        }
        return;
    }
    extern __shared__ char smem[];
    const uint32_t sb = smem_u32(smem);
    const int tid = threadIdx.x, wid = tid >> 5, lane = tid & 31;
    const int rowbase = blockIdx.x * 128;

    const uint4* bh = (const uint4*)Bhi;
    const uint4* bl = (const uint4*)Blo;
#pragma unroll
    for (int i = tid; i < 1024; i += 256) {
        ((uint4*)(smem + SMB_HI))[i] = bh[i];
        ((uint4*)(smem + SMB_LO))[i] = bl[i];
    }
    if (PRE) {
        const uint4* ah = (const uint4*)(Ahi + (size_t)rowbase * 128);
        const uint4* al = (const uint4*)(Alo + (size_t)rowbase * 128);
#pragma unroll
        for (int i = tid; i < 1024; i += 256) {
            ((uint4*)(smem + SMA_HI))[i] = ah[i];
            ((uint4*)(smem + SMA_LO))[i] = al[i];
        }
    } else {
#pragma unroll
        for (int i = tid; i < 4096; i += 256) {
            int r = i >> 5, kp = i & 31;
            int row = rowbase + r;
            float2 v = (row < N) ? *(const float2*)&X[row * 64 + 2 * kp]
                                 : make_float2(0.f, 0.f);
            uint16_t h0, l0, h1, l1;
            bf16_split(v.x, h0, l0);
            bf16_split(v.y, h1, l1);
            uint32_t off = swz_off(r, kp * 4);
            *(uint32_t*)(smem + SMA_HI + off) = (uint32_t)h0 | ((uint32_t)h1 << 16);
            *(uint32_t*)(smem + SMA_LO + off) = (uint32_t)l0 | ((uint32_t)l1 << 16);
        }
    }
    __syncthreads();

    const int m0 = (wid & 3) * 32;
    const int n0 = (wid >> 2) * 64;
    const int rl  = lane & 7;
    const int grp = lane >> 3;

    float acc[2][8][4];
#pragma unroll
    for (int mt = 0; mt < 2; mt++)
#pragma unroll
        for (int nt = 0; nt < 8; nt++)
#pragma unroll
            for (int j = 0; j < 4; j++) acc[mt][nt][j] = 0.f;

#pragma unroll
    for (int ks = 0; ks < 4; ks++) {
        const int cb = ks * 32;
        uint32_t ahi[2][4], alo[2][4];
#pragma unroll
        for (int mt = 0; mt < 2; mt++) {
            int arow = m0 + mt * 16 + (grp & 1) * 8 + rl;
            int abyte = cb + (grp >> 1) * 16;
            ldm_x4(ahi[mt], sb + SMA_HI + swz_off(arow, abyte));
            ldm_x4(alo[mt], sb + SMA_LO + swz_off(arow, abyte));
        }
#pragma unroll
        for (int np = 0; np < 4; np++) {
            int brow = n0 + np * 16 + (grp >> 1) * 8 + rl;
            int bbyte = cb + (grp & 1) * 16;
            uint32_t bhi[4], blo[4];
            ldm_x4(bhi, sb + SMB_HI + swz_off(brow, bbyte));
            ldm_x4(blo, sb + SMB_LO + swz_off(brow, bbyte));
            mma_bf16(acc[0][2 * np],     ahi[0], bhi[0], bhi[1]);
            mma_bf16(acc[1][2 * np],     ahi[1], bhi[0], bhi[1]);
            mma_bf16(acc[0][2 * np + 1], ahi[0], bhi[2], bhi[3]);
            mma_bf16(acc[1][2 * np + 1], ahi[1], bhi[2], bhi[3]);
            mma_bf16(acc[0][2 * np],     alo[0], bhi[0], bhi[1]);
            mma_bf16(acc[1][2 * np],     alo[1], bhi[0], bhi[1]);
            mma_bf16(acc[0][2 * np + 1], alo[0], bhi[2], bhi[3]);
            mma_bf16(acc[1][2 * np + 1], alo[1], bhi[2], bhi[3]);
            mma_bf16(acc[0][2 * np],     ahi[0], blo[0], blo[1]);
            mma_bf16(acc[1][2 * np],     ahi[1], blo[0], blo[1]);
            mma_bf16(acc[0][2 * np + 1], ahi[0], blo[2], blo[3]);
            mma_bf16(acc[1][2 * np + 1], ahi[1], blo[2], blo[3]);
        }
    }

    const int qr = lane >> 2, qc = (lane & 3) * 2;
#pragma unroll
    for (int mt = 0; mt < 2; mt++) {
#pragma unroll
        for (int nt = 0; nt < 8; nt++) {
            int col = n0 + nt * 8 + qc;
            int row0 = rowbase + m0 + mt * 16 + qr;
#pragma unroll
            for (int h = 0; h < 2; h++) {
                int row = row0 + h * 8;
                if (row < N) {
                    float vx = acc[mt][nt][2 * h], vy = acc[mt][nt][2 * h + 1];
                    if (col < 64) Y0h[row * 32 + (col >> 1)] = __floats2half2_rn(vx, vy);
                    else          *(float2*)&Y1[row * 64 + col - 64] = make_float2(vx, vy);
                }
            }
        }
    }
}

// ---------------------------------------------------------------------------
// Layer-3 fused GEMM: Y[128 x 256] = H @ [W3l | W3r], H from pre-split images.
// ---------------------------------------------------------------------------
#define SM3_AHI 0
#define SM3_ALO 16384
#define SM3_BHI 32768
#define SM3_BLO 65536
#define SM3_TOT 98304

__global__ void __launch_bounds__(512) k_mma3(const unsigned char* __restrict__ Ahi,
                                              const unsigned char* __restrict__ Alo,
                                              const unsigned char* __restrict__ Bhi2,
                                              const unsigned char* __restrict__ Blo2,
                                              const unsigned char* __restrict__ Bhi3,
                                              const unsigned char* __restrict__ Blo3,
                                              __half2* __restrict__ Y0h,
                                              float* __restrict__ Y1, int N) {
    extern __shared__ char smem[];
    const uint32_t sb = smem_u32(smem);
    const int tid = threadIdx.x, wid = tid >> 5, lane = tid & 31;
    const int rowbase = blockIdx.x * 128;

#pragma unroll
    for (int i = tid; i < 2048; i += 512) {
        ((uint4*)(smem + SM3_BHI))[i] = (i < 1024) ? ((const uint4*)Bhi2)[i]
                                                   : ((const uint4*)Bhi3)[i - 1024];
        ((uint4*)(smem + SM3_BLO))[i] = (i < 1024) ? ((const uint4*)Blo2)[i]
                                                   : ((const uint4*)Blo3)[i - 1024];
    }
    {
        const uint4* ah = (const uint4*)(Ahi + (size_t)rowbase * 128);
        const uint4* al = (const uint4*)(Alo + (size_t)rowbase * 128);
#pragma unroll
        for (int i = tid; i < 1024; i += 512) {
            ((uint4*)(smem + SM3_AHI))[i] = ah[i];
            ((uint4*)(smem + SM3_ALO))[i] = al[i];
        }
    }
    __syncthreads();

    const int m0 = (wid & 3) * 32;
    const int n0 = (wid >> 2) * 64;  // 0,64,128,192
    const int rl  = lane & 7;
    const int grp = lane >> 3;

    float acc[2][8][4];
#pragma unroll
    for (int mt = 0; mt < 2; mt++)
#pragma unroll
        for (int nt = 0; nt < 8; nt++)
#pragma unroll
            for (int j = 0; j < 4; j++) acc[mt][nt][j] = 0.f;

#pragma unroll
    for (int ks = 0; ks < 4; ks++) {
        const int cb = ks * 32;
        uint32_t ahi[2][4], alo[2][4];
#pragma unroll
        for (int mt = 0; mt < 2; mt++) {
            int arow = m0 + mt * 16 + (grp & 1) * 8 + rl;
            int abyte = cb + (grp >> 1) * 16;
            ldm_x4(ahi[mt], sb + SM3_AHI + swz_off(arow, abyte));
            ldm_x4(alo[mt], sb + SM3_ALO + swz_off(arow, abyte));
        }
#pragma unroll
        for (int np = 0; np < 4; np++) {
            int brow = n0 + np * 16 + (grp >> 1) * 8 + rl;
            int bbyte = cb + (grp & 1) * 16;
            uint32_t bhi[4], blo[4];
            ldm_x4(bhi, sb + SM3_BHI + swz_off(brow, bbyte));
            ldm_x4(blo, sb + SM3_BLO + swz_off(brow, bbyte));
            mma_bf16(acc[0][2 * np],     ahi[0], bhi[0], bhi[1]);
            mma_bf16(acc[1][2 * np],     ahi[1], bhi[0], bhi[1]);
            mma_bf16(acc[0][2 * np + 1], ahi[0], bhi[2], bhi[3]);
            mma_bf16(acc[1][2 * np + 1], ahi[1], bhi[2], bhi[3]);
            mma_bf16(acc[0][2 * np],     alo[0], bhi[0], bhi[1]);
            mma_bf16(acc[1][2 * np],     alo[1], bhi[0], bhi[1]);
            mma_bf16(acc[0][2 * np + 1], alo[0], bhi[2], bhi[3]);
            mma_bf16(acc[1][2 * np + 1], alo[1], bhi[2], bhi[3]);
            mma_bf16(acc[0][2 * np],     ahi[0], blo[0], blo[1]);
            mma_bf16(acc[1][2 * np],     ahi[1], blo[0], blo[1]);
            mma_bf16(acc[0][2 * np + 1], ahi[0], blo[2], blo[3]);
            mma_bf16(acc[1][2 * np + 1], ahi[1], blo[2], blo[3]);
        }
    }

    const int qr = lane >> 2, qc = (lane & 3) * 2;
#pragma unroll
    for (int mt = 0; mt < 2; mt++) {
#pragma unroll
        for (int nt = 0; nt < 8; nt++) {
            int col = n0 + nt * 8 + qc;
            int row0 = rowbase + m0 + mt * 16 + qr;
#pragma unroll
            for (int h = 0; h < 2; h++) {
                int row = row0 + h * 8;
                if (row < N) {
                    float vx = acc[mt][nt][2 * h], vy = acc[mt][nt][2 * h + 1];
                    if (col < 128) Y0h[row * 64 + (col >> 1)] = __floats2half2_rn(vx, vy);
                    else           *(float2*)&Y1[row * 128 + col - 128] = make_float2(vx, vy);
                }
            }
        }
    }
}

// ---------------------------------------------------------------------------
// Edge phase
// ---------------------------------------------------------------------------
__device__ __forceinline__ float leaky(float t) { return fmaxf(t, 0.2f * t); }

__device__ __forceinline__ float red8(float p) {
    p += __shfl_xor_sync(0xffffffffu, p, 4);
    p += __shfl_xor_sync(0xffffffffu, p, 2);
    p += __shfl_xor_sync(0xffffffffu, p, 1);
    return p;
}
__device__ __forceinline__ float red4(float p) {
    p += __shfl_xor_sync(0xffffffffu, p, 2);
    p += __shfl_xor_sync(0xffffffffu, p, 1);
    return p;
}
__device__ __forceinline__ float4 h2f4(uint2 u) {
    float2 lohalf = __half22float2(*(__half2*)&u.x);
    float2 hihalf = __half22float2(*(__half2*)&u.y);
    return make_float4(lohalf.x, lohalf.y, hihalf.x, hihalf.y);
}

// k_edge64: two nodes per warp (16 lanes each, 4 fp16 feats/lane), 4-edge
// pipeline, branchless lockstep, quad-merged online softmax. Output = ELU(..)
// written as pre-split bf16 hi/lo global images (swizzled GEMM layout).
__global__ void k_edge64(const __half2* __restrict__ XLH, const float* __restrict__ XR,
                         const float* __restrict__ att, const float* __restrict__ bias,
                         uint2* __restrict__ OHI, uint2* __restrict__ OLO, int N) {
    const int lane = threadIdx.x & 31;
    const int hl   = lane & 15;
    const int wg   = (blockIdx.x * blockDim.x + threadIdx.x) >> 5;
    const int n    = wg * 2 + (lane >> 4);
    const bool valid = n < N;
    const int nc = valid ? n : N - 1;

    const uint2* XL2 = (const uint2*)XLH;

    float4 a  = *(const float4*)&att[4 * hl];
    float4 xr = *(const float4*)&XR[nc * 64 + 4 * hl];
    float4 vs = h2f4(XL2[nc * 16 + hl]);

    auto score = [&](const float4& v) {
        return a.x * leaky(v.x + xr.x) + a.y * leaky(v.y + xr.y) +
               a.z * leaky(v.z + xr.z) + a.w * leaky(v.w + xr.w);
    };

    float m = red4(score(vs));
    float d = 1.f;
    float4 acc = vs;

    int beg = g_rowptr[nc];
    int end = valid ? g_rowptr[nc + 1] : beg;
    int cnt = end - beg;
    int ocnt = __shfl_xor_sync(0xffffffffu, cnt, 16);
    int nq = (max(cnt, ocnt) + 3) >> 2;

    int j = beg;
    int s0 = (j + 0 < end) ? g_adj[j + 0] : nc;
    int s1 = (j + 1 < end) ? g_adj[j + 1] : nc;
    int s2 = (j + 2 < end) ? g_adj[j + 2] : nc;
    int s3 = (j + 3 < end) ? g_adj[j + 3] : nc;

    for (int q = 0; q < nq; q++) {
        float4 v0 = h2f4(XL2[s0 * 16 + hl]);
        float4 v1 = h2f4(XL2[s1 * 16 + hl]);
        float4 v2 = h2f4(XL2[s2 * 16 + hl]);
        float4 v3 = h2f4(XL2[s3 * 16 + hl]);
        bool o0 = j + 0 < end, o1 = j + 1 < end, o2 = j + 2 < end, o3 = j + 3 < end;
        int jn = j + 4;
        s0 = (jn + 0 < end) ? g_adj[jn + 0] : nc;
        s1 = (jn + 1 < end) ? g_adj[jn + 1] : nc;
        s2 = (jn + 2 < end) ? g_adj[jn + 2] : nc;
        s3 = (jn + 3 < end) ? g_adj[jn + 3] : nc;
        j = jn;

        float p0 = red4(score(v0));
        float p1 = red4(score(v1));
        float p2 = red4(score(v2));
        float p3 = red4(score(v3));
        p0 = o0 ? p0 : -1e30f;
        p1 = o1 ? p1 : -1e30f;
        p2 = o2 ? p2 : -1e30f;
        p3 = o3 ? p3 : -1e30f;

        float mq = fmaxf(fmaxf(p0, p1), fmaxf(p2, p3));
        float mn = fmaxf(m, mq);
        float w  = __expf(m - mn);
        float e0 = __expf(p0 - mn), e1 = __expf(p1 - mn);
        float e2 = __expf(p2 - mn), e3 = __expf(p3 - mn);
        acc.x = acc.x * w + (e0 * v0.x + e1 * v1.x) + (e2 * v2.x + e3 * v3.x);
        acc.y = acc.y * w + (e0 * v0.y + e1 * v1.y) + (e2 * v2.y + e3 * v3.y);
        acc.z = acc.z * w + (e0 * v0.z + e1 * v1.z) + (e2 * v2.z + e3 * v3.z);
        acc.w = acc.w * w + (e0 * v0.w + e1 * v1.w) + (e2 * v2.w + e3 * v3.w);
        d = d * w + ((e0 + e1) + (e2 + e3));
        m = mn;
    }
    float inv = 1.f / d;
    float o0 = acc.x * inv + bias[4 * hl + 0];
    float o1 = acc.y * inv + bias[4 * hl + 1];
    float o2 = acc.z * inv + bias[4 * hl + 2];
    float o3 = acc.w * inv + bias[4 * hl + 3];
    o0 = o0 > 0.f ? o0 : (__expf(o0) - 1.f);
    o1 = o1 > 0.f ? o1 : (__expf(o1) - 1.f);
    o2 = o2 > 0.f ? o2 : (__expf(o2) - 1.f);
    o3 = o3 > 0.f ? o3 : (__expf(o3) - 1.f);
    if (valid) {
        uint16_t h0, l0, h1, l1, h2, l2, h3, l3;
        bf16_split(o0, h0, l0);
        bf16_split(o1, h1, l1);
        bf16_split(o2, h2, l2);
        bf16_split(o3, h3, l3);
        int idx = n * 16 + (hl ^ ((n & 7) << 1));   // swizzled 8B-unit offset
        OHI[idx] = make_uint2((uint32_t)h0 | ((uint32_t)h1 << 16),
                              (uint32_t)h2 | ((uint32_t)h3 << 16));
        OLO[idx] = make_uint2((uint32_t)l0 | ((uint32_t)l1 << 16),
                              (uint32_t)l2 | ((uint32_t)l3 << 16));
    }
}

__global__ void k_edge128_mean(const __half2* __restrict__ XLH, const float* __restrict__ XR,
                               const float* __restrict__ att, const float* __restrict__ bias,
                               float* __restrict__ OUT, int N) {
    int lane = threadIdx.x & 31;
    int n    = (blockIdx.x * blockDim.x + threadIdx.x) >> 5;
    if (n >= N) return;

    float4 a  = *(const float4*)&att[4 * lane];
    float4 xr = *(const float4*)&XR[n * 128 + 4 * lane];
    float4 vs = h2f4(*(const uint2*)&XLH[n * 64 + 2 * lane]);

    auto score = [&](const float4& v) {
        return a.x * leaky(v.x + xr.x) + a.y * leaky(v.y + xr.y) +
               a.z * leaky(v.z + xr.z) + a.w * leaky(v.w + xr.w);
    };

    float m = red8(score(vs));
    float d = 1.f;
    float4 acc = vs;

    int beg = g_rowptr[n], end = g_rowptr[n + 1];
    int i = beg;
    int s0 = 0, s1 = 0, s2 = 0, s3 = 0;
    if (i + 4 <= end) { s0 = g_adj[i]; s1 = g_adj[i+1]; s2 = g_adj[i+2]; s3 = g_adj[i+3]; }
    while (i + 4 <= end) {
        float4 v0 = h2f4(*(const uint2*)&XLH[s0 * 64 + 2 * lane]);
        float4 v1 = h2f4(*(const uint2*)&XLH[s1 * 64 + 2 * lane]);
        float4 v2 = h2f4(*(const uint2*)&XLH[s2 * 64 + 2 * lane]);
        float4 v3 = h2f4(*(const uint2*)&XLH[s3 * 64 + 2 * lane]);
        i += 4;
        if (i + 4 <= end) { s0 = g_adj[i]; s1 = g_adj[i+1]; s2 = g_adj[i+2]; s3 = g_adj[i+3]; }
        float p0 = score(v0), p1 = score(v1), p2 = score(v2), p3 = score(v3);
#pragma unroll
        for (int o = 4; o > 0; o >>= 1) {
            p0 += __shfl_xor_sync(0xffffffffu, p0, o);
            p1 += __shfl_xor_sync(0xffffffffu, p1, o);
            p2 += __shfl_xor_sync(0xffffffffu, p2, o);
            p3 += __shfl_xor_sync(0xffffffffu, p3, o);
        }
        float mq = fmaxf(fmaxf(p0, p1), fmaxf(p2, p3));
        float mn = fmaxf(m, mq);
        float w  = __expf(m - mn);
        float e0 = __expf(p0 - mn), e1 = __expf(p1 - mn);
        float e2 = __expf(p2 - mn), e3 = __expf(p3 - mn);
        acc.x = acc.x * w + (e0 * v0.x + e1 * v1.x) + (e2 * v2.x + e3 * v3.x);
        acc.y = acc.y * w + (e0 * v0.y + e1 * v1.y) + (e2 * v2.y + e3 * v3.y);
        acc.z = acc.z * w + (e0 * v0.z + e1 * v1.z) + (e2 * v2.z + e3 * v3.z);
        acc.w = acc.w * w + (e0 * v0.w + e1 * v1.w) + (e2 * v2.w + e3 * v3.w);
        d = d * w + ((e0 + e1) + (e2 + e3));
        m = mn;
    }
    for (; i < end; i++) {
        int s = g_adj[i];
        float4 v = h2f4(*(const uint2*)&XLH[s * 64 + 2 * lane]);
        float p = red8(score(v));
        float mn = fmaxf(m, p);
        float w  = __expf(m - mn);
        float e  = __expf(p - mn);
        acc.x = acc.x * w + e * v.x;
        acc.y = acc.y * w + e * v.y;
        acc.z = acc.z * w + e * v.z;
        acc.w = acc.w * w + e * v.w;
        d = d * w + e;
        m = mn;
    }
    float inv = 1.f / d;
    float o0 = acc.x * inv, o1 = acc.y * inv, o2 = acc.z * inv, o3 = acc.w * inv;
#pragma unroll
    for (int off = 8; off <= 16; off <<= 1) {
        o0 += __shfl_xor_sync(0xffffffffu, o0, off);
        o1 += __shfl_xor_sync(0xffffffffu, o1, off);
        o2 += __shfl_xor_sync(0xffffffffu, o2, off);
        o3 += __shfl_xor_sync(0xffffffffu, o3, off);
    }
    if (lane < 8) {
        int c = 4 * lane;
        float4 o = make_float4(0.25f * o0 + bias[c + 0],
                               0.25f * o1 + bias[c + 1],
                               0.25f * o2 + bias[c + 2],
                               0.25f * o3 + bias[c + 3]);
        *(float4*)&OUT[n * 32 + c] = o;
    }
}

// ---------------------------------------------------------------------------
// Launch
// ---------------------------------------------------------------------------
extern "C" void kernel_launch(void* const* d_in, const int* in_sizes, int n_in,
                              void* d_out, int out_size) {
    const float* x   = (const float*)d_in[0];
    const int*   ei  = (const int*)  d_in[1];
    const float* W1l = (const float*)d_in[2];
    const float* W1r = (const float*)d_in[3];
    const float* a1  = (const float*)d_in[4];
    const float* b1  = (const float*)d_in[5];
    const float* W2l = (const float*)d_in[6];
    const float* W2r = (const float*)d_in[7];
    const float* a2  = (const float*)d_in[8];
    const float* b2  = (const float*)d_in[9];
    const float* W3l = (const float*)d_in[10];
    const float* W3r = (const float*)d_in[11];
    const float* a3  = (const float*)d_in[12];
    const float* b3  = (const float*)d_in[13];
    float* out = (float*)d_out;

    const int N = in_sizes[0] / 64;
    const int E = in_sizes[1] / 2;
    const int NB = (N + 1023) / 1024;

    float *xlf, *xr;
    unsigned char *hhi, *hlo;
    unsigned char (*whi)[16384], (*wlo)[16384];
    cudaGetSymbolAddress((void**)&xlf, g_xl);
    cudaGetSymbolAddress((void**)&xr,  g_xr);
    cudaGetSymbolAddress((void**)&hhi, g_hhi);
    cudaGetSymbolAddress((void**)&hlo, g_hlo);
    cudaGetSymbolAddress((void**)&whi, g_wimg_hi);
    cudaGetSymbolAddress((void**)&wlo, g_wimg_lo);
    __half2* xlh = (__half2*)xlf;

    cudaFuncSetAttribute(k_mma<false>, cudaFuncAttributeMaxDynamicSharedMemorySize, SM_TOT);
    cudaFuncSetAttribute(k_mma<true>,  cudaFuncAttributeMaxDynamicSharedMemorySize, SM_TOT);
    cudaFuncSetAttribute(k_mma3, cudaFuncAttributeMaxDynamicSharedMemorySize, SM3_TOT);

    const int GT  = (N + 127) / 128;
    const int EB  = (N + 15) / 16;    // edge64: 8 warps x 2 nodes per block
    const int EBM = (N + 7) / 8;      // edge128: 8 warps x 1 node per block

    // 0: W images + edge histogram + bsum zero (g_cnt zero-at-entry invariant)
    k_hist<<<64 + 1024, 256>>>(ei, E, W1l, W1r, W2l, W2r, W3l, W3r);
    // 1: fused decoupled-lookback scan (also re-zeroes g_cnt)
    k_scan<<<NB, 1024>>>(N, E);
    // 2: layer-1 GEMM + scatter side-grid (scatter hidden under GEMM)
    k_mma<false><<<GT + 1024, 256, SM_TOT>>>(x, nullptr, nullptr, whi[0], wlo[0],
                                             xlh, xr, N, ei, E, GT);
    // 3: layer-1 edge -> pre-split h images
    k_edge64<<<EB, 256>>>(xlh, xr, a1, b1, (uint2*)hhi, (uint2*)hlo, N);
    // 4: layer-2 GEMM (pre-split A)
    k_mma<true><<<GT, 256, SM_TOT>>>(nullptr, hhi, hlo, whi[1], wlo[1],
                                     xlh, xr, N, nullptr, 0, GT);
    // 5: layer-2 edge
    k_edge64<<<EB, 256>>>(xlh, xr, a2, b2, (uint2*)hhi, (uint2*)hlo, N);
    // 6: layer-3 fused dual-N GEMM (pre-split A)
    k_mma3<<<GT, 512, SM3_TOT>>>(hhi, hlo, whi[2], wlo[2], whi[3], wlo[3], xlh, xr, N);
    // 7: layer-3 edge (mean over heads) -> final output
    k_edge128_mean<<<EBM, 256>>>(xlh, xr, a3, b3, out, N);
}

// round 15
// speedup vs baseline: 1.5298x; 1.0164x over previous
#include <cuda_runtime.h>
#include <cuda_bf16.h>
#include <cuda_fp16.h>
#include <cstdint>

// Problem constants
#define NMAX 100000
#define EMAX 800000
#define HPAD 100096   // NMAX rounded up to 128 (tile padding)

// Scratch (no allocation allowed -> __device__ globals)
// g_cnt/g_bsum rely on zero-at-entry: zero at module load, re-zeroed by
// k_scan (g_cnt) and k_hist (g_bsum) every call.
// g_adj padded +16: edge kernels prefetch unconditionally past `end`
// (pad values are other nodes' entries or zero -> valid indices; masked out).
__device__ float g_xl[NMAX * 128];     // fp16 xl (half2) buffers
__device__ float g_xr[NMAX * 128];     // fp32 xr
__device__ __align__(16) unsigned char g_hhi[HPAD * 128];  // h bf16-hi image (swizzled)
__device__ __align__(16) unsigned char g_hlo[HPAD * 128];  // h bf16-lo image (swizzled)
__device__ int   g_cnt[NMAX];
__device__ int   g_rowptr[NMAX + 1];
__device__ int   g_fill[NMAX];
__device__ int   g_adj[EMAX + 16];
__device__ int   g_bsum[128];
// bf16 [n=128][k=64] W images (XOR-swizzled): 0:[W1l|W1r] 1:[W2l|W2r] 2:W3l 3:W3r
__device__ __align__(16) unsigned char g_wimg_hi[4][16384];
__device__ __align__(16) unsigned char g_wimg_lo[4][16384];

// ---------------------------------------------------------------------------
// helpers
// ---------------------------------------------------------------------------
__device__ __forceinline__ uint32_t smem_u32(const void* p) {
    uint32_t a;
    asm("{ .reg .u64 t; cvta.to.shared.u64 t, %1; cvt.u32.u64 %0, t; }" : "=r"(a) : "l"(p));
    return a;
}
__device__ __forceinline__ void bf16_split(float v, uint16_t& hi, uint16_t& lo) {
    __nv_bfloat16 h = __float2bfloat16(v);
    float residual = v - __bfloat162float(h);
    __nv_bfloat16 l = __float2bfloat16(residual);
    hi = *(uint16_t*)&h;
    lo = *(uint16_t*)&l;
}
__device__ __forceinline__ void ldm_x4(uint32_t (&r)[4], uint32_t addr) {
    asm volatile("ldmatrix.sync.aligned.m8n8.x4.shared.b16 {%0,%1,%2,%3}, [%4];"
                 : "=r"(r[0]), "=r"(r[1]), "=r"(r[2]), "=r"(r[3]) : "r"(addr));
}
__device__ __forceinline__ void mma_bf16(float (&d)[4], const uint32_t (&a)[4],
                                         uint32_t b0, uint32_t b1) {
    asm volatile(
        "mma.sync.aligned.m16n8k16.row.col.f32.bf16.bf16.f32 "
        "{%0,%1,%2,%3}, {%4,%5,%6,%7}, {%8,%9}, {%0,%1,%2,%3};"
        : "+f"(d[0]), "+f"(d[1]), "+f"(d[2]), "+f"(d[3])
        : "r"(a[0]), "r"(a[1]), "r"(a[2]), "r"(a[3]), "r"(b0), "r"(b1));
}
// XOR swizzle inside a 128B row: 16B chunk index XORed with (row&7)
__device__ __forceinline__ uint32_t swz_off(int row, int byte_in_row) {
    return (uint32_t)(row * 128 + (byte_in_row ^ ((row & 7) << 4)));
}

// ---------------------------------------------------------------------------
// k_hist: blocks 0-63 build W bf16 hi/lo images; blocks 64+ run the edge
// histogram; block 64 zeroes bsum. (W images complete BEFORE any GEMM launch.)
// ---------------------------------------------------------------------------
__global__ void k_hist(const int* __restrict__ ei, int E,
                       const float* __restrict__ W1l, const float* __restrict__ W1r,
                       const float* __restrict__ W2l, const float* __restrict__ W2r,
                       const float* __restrict__ W3l, const float* __restrict__ W3r) {
    if (blockIdx.x >= 64) {
        if (blockIdx.x == 64 && threadIdx.x < 128) g_bsum[threadIdx.x] = 0;
        for (int i = (blockIdx.x - 64) * 256 + threadIdx.x; i < E; i += 1024 * 256)
            atomicAdd(&g_cnt[ei[E + i]], 1);
        return;
    }
    int tid = blockIdx.x * 256 + threadIdx.x;   // 0..16383
    int img = tid >> 12, idx = tid & 4095;
    int n = idx >> 5, kp = idx & 31;
    int k0 = 2 * kp, k1 = k0 + 1;
    float v0, v1;
    if (img == 0) {
        v0 = (n < 64) ? W1l[k0 * 64 + n] : W1r[k0 * 64 + n - 64];
        v1 = (n < 64) ? W1l[k1 * 64 + n] : W1r[k1 * 64 + n - 64];
    } else if (img == 1) {
        v0 = (n < 64) ? W2l[k0 * 64 + n] : W2r[k0 * 64 + n - 64];
        v1 = (n < 64) ? W2l[k1 * 64 + n] : W2r[k1 * 64 + n - 64];
    } else if (img == 2) {
        v0 = W3l[k0 * 128 + n];
        v1 = W3l[k1 * 128 + n];
    } else {
        v0 = W3r[k0 * 128 + n];
        v1 = W3r[k1 * 128 + n];
    }
    uint16_t h0, l0, h1, l1;
    bf16_split(v0, h0, l0);
    bf16_split(v1, h1, l1);
    uint32_t off = swz_off(n, kp * 4);
    *(uint32_t*)(g_wimg_hi[img] + off) = (uint32_t)h0 | ((uint32_t)h1 << 16);
    *(uint32_t*)(g_wimg_lo[img] + off) = (uint32_t)l0 | ((uint32_t)l1 << 16);
}

// ---------------------------------------------------------------------------
// CSR: fused decoupled-lookback scan (NB <= 148 blocks, all co-resident).
// Also re-zeroes g_cnt for the next replay.
// ---------------------------------------------------------------------------
__device__ __forceinline__ int block_scan_excl_1024(int val, int& total) {
    __shared__ int wsum[32];
    int lane = threadIdx.x & 31, w = threadIdx.x >> 5;
    int inc = val;
#pragma unroll
    for (int o = 1; o < 32; o <<= 1) {
        int u = __shfl_up_sync(0xffffffffu, inc, o);
        if (lane >= o) inc += u;
    }
    if (lane == 31) wsum[w] = inc;
    __syncthreads();
    if (w == 0) {
        int v = wsum[lane];
#pragma unroll
        for (int o = 1; o < 32; o <<= 1) {
            int u = __shfl_up_sync(0xffffffffu, v, o);
            if (lane >= o) v += u;
        }
        wsum[lane] = v;
    }
    __syncthreads();
    int off = (w > 0) ? wsum[w - 1] : 0;
    total = wsum[31];
    return off + inc - val;
}

__global__ void k_scan(int N, int E) {
    int b = blockIdx.x, t = threadIdx.x;
    int idx = b * 1024 + t;
    int val = (idx < N) ? g_cnt[idx] : 0;
    if (idx < N) g_cnt[idx] = 0;                 // re-zero for next replay
    int total;
    int ex = block_scan_excl_1024(val, total);
    if (t == 0) atomicExch(&g_bsum[b], total + 1);   // publish (sentinel +1)
    int my = 0;
    if (t < b) {
        int v;
        do { v = atomicAdd(&g_bsum[t], 0); } while (v == 0);
        my = v - 1;
    }
    __shared__ int red[32];
    int lane = t & 31, w = t >> 5;
#pragma unroll
    for (int o = 16; o > 0; o >>= 1) my += __shfl_xor_sync(0xffffffffu, my, o);
    if (lane == 0) red[w] = my;
    __syncthreads();
    if (t == 0) {
        int s = 0;
#pragma unroll
        for (int i = 0; i < 32; i++) s += red[i];
        red[0] = s;
    }
    __syncthreads();
    int off = red[0];
    if (idx < N) {
        g_rowptr[idx] = ex + off;
        g_fill[idx]   = ex + off;
    }
    if (b == 0 && t == 0) g_rowptr[N] = E;
}

// ---------------------------------------------------------------------------
// HMMA GEMM (layers 1/2): Y[128x128] = X @ [Wl|Wr], 3-term bf16 split.
// PRE=false: convert fp32 X in-kernel; extra blocks run the CSR SCATTER.
// PRE=true : A loaded from pre-split global bf16 hi/lo images (uint4 copy).
// Epilogue: cols<64 -> fp16 xl, cols>=64 -> fp32 xr.
// ---------------------------------------------------------------------------
#define SMA_HI 0
#define SMA_LO 16384
#define SMB_HI 32768
#define SMB_LO 49152
#define SM_TOT 65536

template <bool PRE>
__global__ void __launch_bounds__(256, 2) k_mma(const float* __restrict__ X,
                                                const unsigned char* __restrict__ Ahi,
                                                const unsigned char* __restrict__ Alo,
                                                const unsigned char* __restrict__ Bhi,
                                                const unsigned char* __restrict__ Blo,
                                                __half2* __restrict__ Y0h,
                                                float* __restrict__ Y1, int N,
                                                const int* __restrict__ ei, int E, int GB) {
    if (!PRE && blockIdx.x >= (unsigned)GB) {
        // scatter side-grid (needs rowptr from k_scan; independent of GEMM)
        for (int i = (blockIdx.x - GB) * 256 + threadIdx.x; i < E; i += 1024 * 256) {
            int d = ei[E + i];
            int p = atomicAdd(&g_fill[d], 1);
            g_adj[p] = ei[i];
        }
        return;
    }
    extern __shared__ char smem[];
    const uint32_t sb = smem_u32(smem);
    const int tid = threadIdx.x, wid = tid >> 5, lane = tid & 31;
    const int rowbase = blockIdx.x * 128;

    const uint4* bh = (const uint4*)Bhi;
    const uint4* bl = (const uint4*)Blo;
#pragma unroll
    for (int i = tid; i < 1024; i += 256) {
        ((uint4*)(smem + SMB_HI))[i] = bh[i];
        ((uint4*)(smem + SMB_LO))[i] = bl[i];
    }
    if (PRE) {
        const uint4* ah = (const uint4*)(Ahi + (size_t)rowbase * 128);
        const uint4* al = (const uint4*)(Alo + (size_t)rowbase * 128);
#pragma unroll
        for (int i = tid; i < 1024; i += 256) {
            ((uint4*)(smem + SMA_HI))[i] = ah[i];
            ((uint4*)(smem + SMA_LO))[i] = al[i];
        }
    } else {
#pragma unroll
        for (int i = tid; i < 4096; i += 256) {
            int r = i >> 5, kp = i & 31;
            int row = rowbase + r;
            float2 v = (row < N) ? *(const float2*)&X[row * 64 + 2 * kp]
                                 : make_float2(0.f, 0.f);
            uint16_t h0, l0, h1, l1;
            bf16_split(v.x, h0, l0);
            bf16_split(v.y, h1, l1);
            uint32_t off = swz_off(r, kp * 4);
            *(uint32_t*)(smem + SMA_HI + off) = (uint32_t)h0 | ((uint32_t)h1 << 16);
            *(uint32_t*)(smem + SMA_LO + off) = (uint32_t)l0 | ((uint32_t)l1 << 16);
        }
    }
    __syncthreads();

    const int m0 = (wid & 3) * 32;
    const int n0 = (wid >> 2) * 64;
    const int rl  = lane & 7;
    const int grp = lane >> 3;

    float acc[2][8][4];
#pragma unroll
    for (int mt = 0; mt < 2; mt++)
#pragma unroll
        for (int nt = 0; nt < 8; nt++)
#pragma unroll
            for (int j = 0; j < 4; j++) acc[mt][nt][j] = 0.f;

#pragma unroll
    for (int ks = 0; ks < 4; ks++) {
        const int cb = ks * 32;
        uint32_t ahi[2][4], alo[2][4];
#pragma unroll
        for (int mt = 0; mt < 2; mt++) {
            int arow = m0 + mt * 16 + (grp & 1) * 8 + rl;
            int abyte = cb + (grp >> 1) * 16;
            ldm_x4(ahi[mt], sb + SMA_HI + swz_off(arow, abyte));
            ldm_x4(alo[mt], sb + SMA_LO + swz_off(arow, abyte));
        }
#pragma unroll
        for (int np = 0; np < 4; np++) {
            int brow = n0 + np * 16 + (grp >> 1) * 8 + rl;
            int bbyte = cb + (grp & 1) * 16;
            uint32_t bhi[4], blo[4];
            ldm_x4(bhi, sb + SMB_HI + swz_off(brow, bbyte));
            ldm_x4(blo, sb + SMB_LO + swz_off(brow, bbyte));
            mma_bf16(acc[0][2 * np],     ahi[0], bhi[0], bhi[1]);
            mma_bf16(acc[1][2 * np],     ahi[1], bhi[0], bhi[1]);
            mma_bf16(acc[0][2 * np + 1], ahi[0], bhi[2], bhi[3]);
            mma_bf16(acc[1][2 * np + 1], ahi[1], bhi[2], bhi[3]);
            mma_bf16(acc[0][2 * np],     alo[0], bhi[0], bhi[1]);
            mma_bf16(acc[1][2 * np],     alo[1], bhi[0], bhi[1]);
            mma_bf16(acc[0][2 * np + 1], alo[0], bhi[2], bhi[3]);
            mma_bf16(acc[1][2 * np + 1], alo[1], bhi[2], bhi[3]);
            mma_bf16(acc[0][2 * np],     ahi[0], blo[0], blo[1]);
            mma_bf16(acc[1][2 * np],     ahi[1], blo[0], blo[1]);
            mma_bf16(acc[0][2 * np + 1], ahi[0], blo[2], blo[3]);
            mma_bf16(acc[1][2 * np + 1], ahi[1], blo[2], blo[3]);
        }
    }

    const int qr = lane >> 2, qc = (lane & 3) * 2;
#pragma unroll
    for (int mt = 0; mt < 2; mt++) {
#pragma unroll
        for (int nt = 0; nt < 8; nt++) {
            int col = n0 + nt * 8 + qc;
            int row0 = rowbase + m0 + mt * 16 + qr;
#pragma unroll
            for (int h = 0; h < 2; h++) {
                int row = row0 + h * 8;
                if (row < N) {
                    float vx = acc[mt][nt][2 * h], vy = acc[mt][nt][2 * h + 1];
                    if (col < 64) Y0h[row * 32 + (col >> 1)] = __floats2half2_rn(vx, vy);
                    else          *(float2*)&Y1[row * 64 + col - 64] = make_float2(vx, vy);
                }
            }
        }
    }
}

// ---------------------------------------------------------------------------
// Layer-3 fused GEMM: Y[128 x 256] = H @ [W3l | W3r], H from pre-split images.
// ---------------------------------------------------------------------------
#define SM3_AHI 0
#define SM3_ALO 16384
#define SM3_BHI 32768
#define SM3_BLO 65536
#define SM3_TOT 98304

__global__ void __launch_bounds__(512) k_mma3(const unsigned char* __restrict__ Ahi,
                                              const unsigned char* __restrict__ Alo,
                                              const unsigned char* __restrict__ Bhi2,
                                              const unsigned char* __restrict__ Blo2,
                                              const unsigned char* __restrict__ Bhi3,
                                              const unsigned char* __restrict__ Blo3,
                                              __half2* __restrict__ Y0h,
                                              float* __restrict__ Y1, int N) {
    extern __shared__ char smem[];
    const uint32_t sb = smem_u32(smem);
    const int tid = threadIdx.x, wid = tid >> 5, lane = tid & 31;
    const int rowbase = blockIdx.x * 128;

#pragma unroll
    for (int i = tid; i < 2048; i += 512) {
        ((uint4*)(smem + SM3_BHI))[i] = (i < 1024) ? ((const uint4*)Bhi2)[i]
                                                   : ((const uint4*)Bhi3)[i - 1024];
        ((uint4*)(smem + SM3_BLO))[i] = (i < 1024) ? ((const uint4*)Blo2)[i]
                                                   : ((const uint4*)Blo3)[i - 1024];
    }
    {
        const uint4* ah = (const uint4*)(Ahi + (size_t)rowbase * 128);
        const uint4* al = (const uint4*)(Alo + (size_t)rowbase * 128);
#pragma unroll
        for (int i = tid; i < 1024; i += 512) {
            ((uint4*)(smem + SM3_AHI))[i] = ah[i];
            ((uint4*)(smem + SM3_ALO))[i] = al[i];
        }
    }
    __syncthreads();

    const int m0 = (wid & 3) * 32;
    const int n0 = (wid >> 2) * 64;  // 0,64,128,192
    const int rl  = lane & 7;
    const int grp = lane >> 3;

    float acc[2][8][4];
#pragma unroll
    for (int mt = 0; mt < 2; mt++)
#pragma unroll
        for (int nt = 0; nt < 8; nt++)
#pragma unroll
            for (int j = 0; j < 4; j++) acc[mt][nt][j] = 0.f;

#pragma unroll
    for (int ks = 0; ks < 4; ks++) {
        const int cb = ks * 32;
        uint32_t ahi[2][4], alo[2][4];
#pragma unroll
        for (int mt = 0; mt < 2; mt++) {
            int arow = m0 + mt * 16 + (grp & 1) * 8 + rl;
            int abyte = cb + (grp >> 1) * 16;
            ldm_x4(ahi[mt], sb + SM3_AHI + swz_off(arow, abyte));
            ldm_x4(alo[mt], sb + SM3_ALO + swz_off(arow, abyte));
        }
#pragma unroll
        for (int np = 0; np < 4; np++) {
            int brow = n0 + np * 16 + (grp >> 1) * 8 + rl;
            int bbyte = cb + (grp & 1) * 16;
            uint32_t bhi[4], blo[4];
            ldm_x4(bhi, sb + SM3_BHI + swz_off(brow, bbyte));
            ldm_x4(blo, sb + SM3_BLO + swz_off(brow, bbyte));
            mma_bf16(acc[0][2 * np],     ahi[0], bhi[0], bhi[1]);
            mma_bf16(acc[1][2 * np],     ahi[1], bhi[0], bhi[1]);
            mma_bf16(acc[0][2 * np + 1], ahi[0], bhi[2], bhi[3]);
            mma_bf16(acc[1][2 * np + 1], ahi[1], bhi[2], bhi[3]);
            mma_bf16(acc[0][2 * np],     alo[0], bhi[0], bhi[1]);
            mma_bf16(acc[1][2 * np],     alo[1], bhi[0], bhi[1]);
            mma_bf16(acc[0][2 * np + 1], alo[0], bhi[2], bhi[3]);
            mma_bf16(acc[1][2 * np + 1], alo[1], bhi[2], bhi[3]);
            mma_bf16(acc[0][2 * np],     ahi[0], blo[0], blo[1]);
            mma_bf16(acc[1][2 * np],     ahi[1], blo[0], blo[1]);
            mma_bf16(acc[0][2 * np + 1], ahi[0], blo[2], blo[3]);
            mma_bf16(acc[1][2 * np + 1], ahi[1], blo[2], blo[3]);
        }
    }

    const int qr = lane >> 2, qc = (lane & 3) * 2;
#pragma unroll
    for (int mt = 0; mt < 2; mt++) {
#pragma unroll
        for (int nt = 0; nt < 8; nt++) {
            int col = n0 + nt * 8 + qc;
            int row0 = rowbase + m0 + mt * 16 + qr;
#pragma unroll
            for (int h = 0; h < 2; h++) {
                int row = row0 + h * 8;
                if (row < N) {
                    float vx = acc[mt][nt][2 * h], vy = acc[mt][nt][2 * h + 1];
                    if (col < 128) Y0h[row * 64 + (col >> 1)] = __floats2half2_rn(vx, vy);
                    else           *(float2*)&Y1[row * 128 + col - 128] = make_float2(vx, vy);
                }
            }
        }
    }
}

// ---------------------------------------------------------------------------
// Edge phase
// ---------------------------------------------------------------------------
__device__ __forceinline__ float leaky(float t) { return fmaxf(t, 0.2f * t); }

__device__ __forceinline__ float red8(float p) {
    p += __shfl_xor_sync(0xffffffffu, p, 4);
    p += __shfl_xor_sync(0xffffffffu, p, 2);
    p += __shfl_xor_sync(0xffffffffu, p, 1);
    return p;
}
__device__ __forceinline__ float red4(float p) {
    p += __shfl_xor_sync(0xffffffffu, p, 2);
    p += __shfl_xor_sync(0xffffffffu, p, 1);
    return p;
}
__device__ __forceinline__ float4 h2f4(uint2 u) {
    float2 lohalf = __half22float2(*(__half2*)&u.x);
    float2 hihalf = __half22float2(*(__half2*)&u.y);
    return make_float4(lohalf.x, lohalf.y, hihalf.x, hihalf.y);
}

// k_edge64: two nodes per warp (16 lanes each, 4 fp16 feats/lane), 4-edge
// pipeline with UNCONDITIONAL adjacency prefetch (g_adj padded; score masks
// via k<rem), quad-merged online softmax.
__global__ void k_edge64(const __half2* __restrict__ XLH, const float* __restrict__ XR,
                         const float* __restrict__ att, const float* __restrict__ bias,
                         uint2* __restrict__ OHI, uint2* __restrict__ OLO, int N) {
    const int lane = threadIdx.x & 31;
    const int hl   = lane & 15;
    const int wg   = (blockIdx.x * blockDim.x + threadIdx.x) >> 5;
    const int n    = wg * 2 + (lane >> 4);
    const bool valid = n < N;
    const int nc = valid ? n : N - 1;

    const uint2* XL2 = (const uint2*)XLH;

    float4 a  = *(const float4*)&att[4 * hl];
    float4 xr = *(const float4*)&XR[nc * 64 + 4 * hl];
    float4 vs = h2f4(XL2[nc * 16 + hl]);

    auto score = [&](const float4& v) {
        return a.x * leaky(v.x + xr.x) + a.y * leaky(v.y + xr.y) +
               a.z * leaky(v.z + xr.z) + a.w * leaky(v.w + xr.w);
    };

    float m = red4(score(vs));
    float d = 1.f;
    float4 acc = vs;

    int beg = g_rowptr[nc];
    int end = valid ? g_rowptr[nc + 1] : beg;
    int cnt = end - beg;
    int ocnt = __shfl_xor_sync(0xffffffffu, cnt, 16);
    int nq = (max(cnt, ocnt) + 3) >> 2;

    int j = beg;
    int s0 = g_adj[j], s1 = g_adj[j + 1], s2 = g_adj[j + 2], s3 = g_adj[j + 3];

    for (int q = 0; q < nq; q++) {
        float4 v0 = h2f4(XL2[s0 * 16 + hl]);
        float4 v1 = h2f4(XL2[s1 * 16 + hl]);
        float4 v2 = h2f4(XL2[s2 * 16 + hl]);
        float4 v3 = h2f4(XL2[s3 * 16 + hl]);
        int rem = end - j;
        j += 4;
        s0 = g_adj[j]; s1 = g_adj[j + 1]; s2 = g_adj[j + 2]; s3 = g_adj[j + 3];

        float p0 = red4(score(v0));
        float p1 = red4(score(v1));
        float p2 = red4(score(v2));
        float p3 = red4(score(v3));
        p0 = (0 < rem) ? p0 : -1e30f;
        p1 = (1 < rem) ? p1 : -1e30f;
        p2 = (2 < rem) ? p2 : -1e30f;
        p3 = (3 < rem) ? p3 : -1e30f;

        float mq = fmaxf(fmaxf(p0, p1), fmaxf(p2, p3));
        float mn = fmaxf(m, mq);
        float w  = __expf(m - mn);
        float e0 = __expf(p0 - mn), e1 = __expf(p1 - mn);
        float e2 = __expf(p2 - mn), e3 = __expf(p3 - mn);
        acc.x = acc.x * w + (e0 * v0.x + e1 * v1.x) + (e2 * v2.x + e3 * v3.x);
        acc.y = acc.y * w + (e0 * v0.y + e1 * v1.y) + (e2 * v2.y + e3 * v3.y);
        acc.z = acc.z * w + (e0 * v0.z + e1 * v1.z) + (e2 * v2.z + e3 * v3.z);
        acc.w = acc.w * w + (e0 * v0.w + e1 * v1.w) + (e2 * v2.w + e3 * v3.w);
        d = d * w + ((e0 + e1) + (e2 + e3));
        m = mn;
    }
    float inv = 1.f / d;
    float o0 = acc.x * inv + bias[4 * hl + 0];
    float o1 = acc.y * inv + bias[4 * hl + 1];
    float o2 = acc.z * inv + bias[4 * hl + 2];
    float o3 = acc.w * inv + bias[4 * hl + 3];
    o0 = o0 > 0.f ? o0 : (__expf(o0) - 1.f);
    o1 = o1 > 0.f ? o1 : (__expf(o1) - 1.f);
    o2 = o2 > 0.f ? o2 : (__expf(o2) - 1.f);
    o3 = o3 > 0.f ? o3 : (__expf(o3) - 1.f);
    if (valid) {
        uint16_t h0, l0, h1, l1, h2, l2, h3, l3;
        bf16_split(o0, h0, l0);
        bf16_split(o1, h1, l1);
        bf16_split(o2, h2, l2);
        bf16_split(o3, h3, l3);
        int idx = n * 16 + (hl ^ ((n & 7) << 1));   // swizzled 8B-unit offset
        OHI[idx] = make_uint2((uint32_t)h0 | ((uint32_t)h1 << 16),
                              (uint32_t)h2 | ((uint32_t)h3 << 16));
        OLO[idx] = make_uint2((uint32_t)l0 | ((uint32_t)l1 << 16),
                              (uint32_t)l2 | ((uint32_t)l3 << 16));
    }
}

// k_edge128_mean: masked nq-loop (no scalar tail), unconditional prefetch.
__global__ void k_edge128_mean(const __half2* __restrict__ XLH, const float* __restrict__ XR,
                               const float* __restrict__ att, const float* __restrict__ bias,
                               float* __restrict__ OUT, int N) {
    int lane = threadIdx.x & 31;
    int n    = (blockIdx.x * blockDim.x + threadIdx.x) >> 5;
    if (n >= N) return;

    float4 a  = *(const float4*)&att[4 * lane];
    float4 xr = *(const float4*)&XR[n * 128 + 4 * lane];
    float4 vs = h2f4(*(const uint2*)&XLH[n * 64 + 2 * lane]);

    auto score = [&](const float4& v) {
        return a.x * leaky(v.x + xr.x) + a.y * leaky(v.y + xr.y) +
               a.z * leaky(v.z + xr.z) + a.w * leaky(v.w + xr.w);
    };

    float m = red8(score(vs));
    float d = 1.f;
    float4 acc = vs;

    int beg = g_rowptr[n], end = g_rowptr[n + 1];
    int nq = (end - beg + 3) >> 2;
    int j = beg;
    int s0 = g_adj[j], s1 = g_adj[j + 1], s2 = g_adj[j + 2], s3 = g_adj[j + 3];

    for (int q = 0; q < nq; q++) {
        float4 v0 = h2f4(*(const uint2*)&XLH[s0 * 64 + 2 * lane]);
        float4 v1 = h2f4(*(const uint2*)&XLH[s1 * 64 + 2 * lane]);
        float4 v2 = h2f4(*(const uint2*)&XLH[s2 * 64 + 2 * lane]);
        float4 v3 = h2f4(*(const uint2*)&XLH[s3 * 64 + 2 * lane]);
        int rem = end - j;
        j += 4;
        s0 = g_adj[j]; s1 = g_adj[j + 1]; s2 = g_adj[j + 2]; s3 = g_adj[j + 3];

        float p0 = red8(score(v0));
        float p1 = red8(score(v1));
        float p2 = red8(score(v2));
        float p3 = red8(score(v3));
        p0 = (0 < rem) ? p0 : -1e30f;
        p1 = (1 < rem) ? p1 : -1e30f;
        p2 = (2 < rem) ? p2 : -1e30f;
        p3 = (3 < rem) ? p3 : -1e30f;

        float mq = fmaxf(fmaxf(p0, p1), fmaxf(p2, p3));
        float mn = fmaxf(m, mq);
        float w  = __expf(m - mn);
        float e0 = __expf(p0 - mn), e1 = __expf(p1 - mn);
        float e2 = __expf(p2 - mn), e3 = __expf(p3 - mn);
        acc.x = acc.x * w + (e0 * v0.x + e1 * v1.x) + (e2 * v2.x + e3 * v3.x);
        acc.y = acc.y * w + (e0 * v0.y + e1 * v1.y) + (e2 * v2.y + e3 * v3.y);
        acc.z = acc.z * w + (e0 * v0.z + e1 * v1.z) + (e2 * v2.z + e3 * v3.z);
        acc.w = acc.w * w + (e0 * v0.w + e1 * v1.w) + (e2 * v2.w + e3 * v3.w);
        d = d * w + ((e0 + e1) + (e2 + e3));
        m = mn;
    }
    float inv = 1.f / d;
    float o0 = acc.x * inv, o1 = acc.y * inv, o2 = acc.z * inv, o3 = acc.w * inv;
#pragma unroll
    for (int off = 8; off <= 16; off <<= 1) {
        o0 += __shfl_xor_sync(0xffffffffu, o0, off);
        o1 += __shfl_xor_sync(0xffffffffu, o1, off);
        o2 += __shfl_xor_sync(0xffffffffu, o2, off);
        o3 += __shfl_xor_sync(0xffffffffu, o3, off);
    }
    if (lane < 8) {
        int c = 4 * lane;
        float4 o = make_float4(0.25f * o0 + bias[c + 0],
                               0.25f * o1 + bias[c + 1],
                               0.25f * o2 + bias[c + 2],
                               0.25f * o3 + bias[c + 3]);
        *(float4*)&OUT[n * 32 + c] = o;
    }
}

// ---------------------------------------------------------------------------
// Launch: k_hist -> k_scan -> [GEMM1 ‖ scatter] -> edges/GEMMs (R13 structure)
// ---------------------------------------------------------------------------
extern "C" void kernel_launch(void* const* d_in, const int* in_sizes, int n_in,
                              void* d_out, int out_size) {
    const float* x   = (const float*)d_in[0];
    const int*   ei  = (const int*)  d_in[1];
    const float* W1l = (const float*)d_in[2];
    const float* W1r = (const float*)d_in[3];
    const float* a1  = (const float*)d_in[4];
    const float* b1  = (const float*)d_in[5];
    const float* W2l = (const float*)d_in[6];
    const float* W2r = (const float*)d_in[7];
    const float* a2  = (const float*)d_in[8];
    const float* b2  = (const float*)d_in[9];
    const float* W3l = (const float*)d_in[10];
    const float* W3r = (const float*)d_in[11];
    const float* a3  = (const float*)d_in[12];
    const float* b3  = (const float*)d_in[13];
    float* out = (float*)d_out;

    const int N = in_sizes[0] / 64;
    const int E = in_sizes[1] / 2;
    const int NB = (N + 1023) / 1024;

    float *xlf, *xr;
    unsigned char *hhi, *hlo;
    unsigned char (*whi)[16384], (*wlo)[16384];
    cudaGetSymbolAddress((void**)&xlf, g_xl);
    cudaGetSymbolAddress((void**)&xr,  g_xr);
    cudaGetSymbolAddress((void**)&hhi, g_hhi);
    cudaGetSymbolAddress((void**)&hlo, g_hlo);
    cudaGetSymbolAddress((void**)&whi, g_wimg_hi);
    cudaGetSymbolAddress((void**)&wlo, g_wimg_lo);
    __half2* xlh = (__half2*)xlf;

    cudaFuncSetAttribute(k_mma<false>, cudaFuncAttributeMaxDynamicSharedMemorySize, SM_TOT);
    cudaFuncSetAttribute(k_mma<true>,  cudaFuncAttributeMaxDynamicSharedMemorySize, SM_TOT);
    cudaFuncSetAttribute(k_mma3, cudaFuncAttributeMaxDynamicSharedMemorySize, SM3_TOT);

    const int GT  = (N + 127) / 128;
    const int EB  = (N + 15) / 16;    // edge64: 8 warps x 2 nodes per block
    const int EBM = (N + 7) / 8;      // edge128: 8 warps x 1 node per block

    // 0: W images + edge histogram + bsum zero
    k_hist<<<64 + 1024, 256>>>(ei, E, W1l, W1r, W2l, W2r, W3l, W3r);
    // 1: fused decoupled-lookback scan (also re-zeroes g_cnt)
    k_scan<<<NB, 1024>>>(N, E);
    // 2: layer-1 GEMM + scatter side-grid
    k_mma<false><<<GT + 1024, 256, SM_TOT>>>(x, nullptr, nullptr, whi[0], wlo[0],
                                             xlh, xr, N, ei, E, GT);
    // 3: layer-1 edge -> pre-split h images
    k_edge64<<<EB, 256>>>(xlh, xr, a1, b1, (uint2*)hhi, (uint2*)hlo, N);
    // 4: layer-2 GEMM (pre-split A)
    k_mma<true><<<GT, 256, SM_TOT>>>(nullptr, hhi, hlo, whi[1], wlo[1],
                                     xlh, xr, N, nullptr, 0, GT);
    // 5: layer-2 edge
    k_edge64<<<EB, 256>>>(xlh, xr, a2, b2, (uint2*)hhi, (uint2*)hlo, N);
    // 6: layer-3 fused dual-N GEMM (pre-split A)
    k_mma3<<<GT, 512, SM3_TOT>>>(hhi, hlo, whi[2], wlo[2], whi[3], wlo[3], xlh, xr, N);
    // 7: layer-3 edge (mean over heads) -> final output
    k_edge128_mean<<<EBM, 256>>>(xlh, xr, a3, b3, out, N);
}

// round 16
// speedup vs baseline: 1.6926x; 1.1064x over previous
#include <cuda_runtime.h>
#include <cuda_bf16.h>
#include <cuda_fp16.h>
#include <cstdint>

// Problem constants
#define NMAX 100000
#define EMAX 800000
#define HPAD 100096   // NMAX rounded up to 128 (tile padding)

// Scratch (no allocation allowed -> __device__ globals)
// g_cnt/g_bsum rely on zero-at-entry: zero at module load, re-zeroed by
// k_scan (g_cnt) and k_hist (g_bsum) every call.
// g_adj padded +16: edge kernels prefetch unconditionally past `end`
// (pad values are other nodes' entries or zero -> valid indices; masked out).
__device__ float g_xl[NMAX * 128];     // fp16 xl (half2) buffers
__device__ float g_xr[NMAX * 128];     // fp32 xr
__device__ __align__(16) unsigned char g_hhi[HPAD * 128];  // h bf16-hi image (swizzled)
__device__ __align__(16) unsigned char g_hlo[HPAD * 128];  // h bf16-lo image (swizzled)
__device__ int   g_cnt[NMAX];
__device__ int   g_rowptr[NMAX + 1];
__device__ int   g_fill[NMAX];
__device__ int   g_adj[EMAX + 16];
__device__ int   g_bsum[128];
// bf16 [n=128][k=64] W images (XOR-swizzled): 0:[W1l|W1r] 1:[W2l|W2r] 2:W3l 3:W3r
__device__ __align__(16) unsigned char g_wimg_hi[4][16384];
__device__ __align__(16) unsigned char g_wimg_lo[4][16384];

// ---------------------------------------------------------------------------
// helpers
// ---------------------------------------------------------------------------
__device__ __forceinline__ uint32_t smem_u32(const void* p) {
    uint32_t a;
    asm("{ .reg .u64 t; cvta.to.shared.u64 t, %1; cvt.u32.u64 %0, t; }" : "=r"(a) : "l"(p));
    return a;
}
__device__ __forceinline__ void bf16_split(float v, uint16_t& hi, uint16_t& lo) {
    __nv_bfloat16 h = __float2bfloat16(v);
    float residual = v - __bfloat162float(h);
    __nv_bfloat16 l = __float2bfloat16(residual);
    hi = *(uint16_t*)&h;
    lo = *(uint16_t*)&l;
}
__device__ __forceinline__ void ldm_x4(uint32_t (&r)[4], uint32_t addr) {
    asm volatile("ldmatrix.sync.aligned.m8n8.x4.shared.b16 {%0,%1,%2,%3}, [%4];"
                 : "=r"(r[0]), "=r"(r[1]), "=r"(r[2]), "=r"(r[3]) : "r"(addr));
}
__device__ __forceinline__ void mma_bf16(float (&d)[4], const uint32_t (&a)[4],
                                         uint32_t b0, uint32_t b1) {
    asm volatile(
        "mma.sync.aligned.m16n8k16.row.col.f32.bf16.bf16.f32 "
        "{%0,%1,%2,%3}, {%4,%5,%6,%7}, {%8,%9}, {%0,%1,%2,%3};"
        : "+f"(d[0]), "+f"(d[1]), "+f"(d[2]), "+f"(d[3])
        : "r"(a[0]), "r"(a[1]), "r"(a[2]), "r"(a[3]), "r"(b0), "r"(b1));
}
// XOR swizzle inside a 128B row: 16B chunk index XORed with (row&7)
__device__ __forceinline__ uint32_t swz_off(int row, int byte_in_row) {
    return (uint32_t)(row * 128 + (byte_in_row ^ ((row & 7) << 4)));
}

// ---------------------------------------------------------------------------
// k_hist: blocks 0-63 build W bf16 hi/lo images; blocks 64+ run the edge
// histogram; block 64 zeroes bsum. (W images complete BEFORE any GEMM launch.)
// ---------------------------------------------------------------------------
__global__ void k_hist(const int* __restrict__ ei, int E,
                       const float* __restrict__ W1l, const float* __restrict__ W1r,
                       const float* __restrict__ W2l, const float* __restrict__ W2r,
                       const float* __restrict__ W3l, const float* __restrict__ W3r) {
    if (blockIdx.x >= 64) {
        if (blockIdx.x == 64 && threadIdx.x < 128) g_bsum[threadIdx.x] = 0;
        for (int i = (blockIdx.x - 64) * 256 + threadIdx.x; i < E; i += 1024 * 256)
            atomicAdd(&g_cnt[ei[E + i]], 1);
        return;
    }
    int tid = blockIdx.x * 256 + threadIdx.x;   // 0..16383
    int img = tid >> 12, idx = tid & 4095;
    int n = idx >> 5, kp = idx & 31;
    int k0 = 2 * kp, k1 = k0 + 1;
    float v0, v1;
    if (img == 0) {
        v0 = (n < 64) ? W1l[k0 * 64 + n] : W1r[k0 * 64 + n - 64];
        v1 = (n < 64) ? W1l[k1 * 64 + n] : W1r[k1 * 64 + n - 64];
    } else if (img == 1) {
        v0 = (n < 64) ? W2l[k0 * 64 + n] : W2r[k0 * 64 + n - 64];
        v1 = (n < 64) ? W2l[k1 * 64 + n] : W2r[k1 * 64 + n - 64];
    } else if (img == 2) {
        v0 = W3l[k0 * 128 + n];
        v1 = W3l[k1 * 128 + n];
    } else {
        v0 = W3r[k0 * 128 + n];
        v1 = W3r[k1 * 128 + n];
    }
    uint16_t h0, l0, h1, l1;
    bf16_split(v0, h0, l0);
    bf16_split(v1, h1, l1);
    uint32_t off = swz_off(n, kp * 4);
    *(uint32_t*)(g_wimg_hi[img] + off) = (uint32_t)h0 | ((uint32_t)h1 << 16);
    *(uint32_t*)(g_wimg_lo[img] + off) = (uint32_t)l0 | ((uint32_t)l1 << 16);
}

// ---------------------------------------------------------------------------
// CSR: fused decoupled-lookback scan (NB <= 148 blocks, all co-resident).
// Also re-zeroes g_cnt for the next replay.
// ---------------------------------------------------------------------------
__device__ __forceinline__ int block_scan_excl_1024(int val, int& total) {
    __shared__ int wsum[32];
    int lane = threadIdx.x & 31, w = threadIdx.x >> 5;
    int inc = val;
#pragma unroll
    for (int o = 1; o < 32; o <<= 1) {
        int u = __shfl_up_sync(0xffffffffu, inc, o);
        if (lane >= o) inc += u;
    }
    if (lane == 31) wsum[w] = inc;
    __syncthreads();
    if (w == 0) {
        int v = wsum[lane];
#pragma unroll
        for (int o = 1; o < 32; o <<= 1) {
            int u = __shfl_up_sync(0xffffffffu, v, o);
            if (lane >= o) v += u;
        }
        wsum[lane] = v;
    }
    __syncthreads();
    int off = (w > 0) ? wsum[w - 1] : 0;
    total = wsum[31];
    return off + inc - val;
}

__global__ void k_scan(int N, int E) {
    int b = blockIdx.x, t = threadIdx.x;
    int idx = b * 1024 + t;
    int val = (idx < N) ? g_cnt[idx] : 0;
    if (idx < N) g_cnt[idx] = 0;                 // re-zero for next replay
    int total;
    int ex = block_scan_excl_1024(val, total);
    if (t == 0) atomicExch(&g_bsum[b], total + 1);   // publish (sentinel +1)
    int my = 0;
    if (t < b) {
        int v;
        do { v = atomicAdd(&g_bsum[t], 0); } while (v == 0);
        my = v - 1;
    }
    __shared__ int red[32];
    int lane = t & 31, w = t >> 5;
#pragma unroll
    for (int o = 16; o > 0; o >>= 1) my += __shfl_xor_sync(0xffffffffu, my, o);
    if (lane == 0) red[w] = my;
    __syncthreads();
    if (t == 0) {
        int s = 0;
#pragma unroll
        for (int i = 0; i < 32; i++) s += red[i];
        red[0] = s;
    }
    __syncthreads();
    int off = red[0];
    if (idx < N) {
        g_rowptr[idx] = ex + off;
        g_fill[idx]   = ex + off;
    }
    if (b == 0 && t == 0) g_rowptr[N] = E;
}

// ---------------------------------------------------------------------------
// HMMA GEMM (layers 1/2): Y[128x128] = X @ [Wl|Wr], 3-term bf16 split.
// PRE=false: convert fp32 X in-kernel; extra blocks run the CSR SCATTER.
// PRE=true : A loaded from pre-split global bf16 hi/lo images (uint4 copy).
// Epilogue: cols<64 -> fp16 xl, cols>=64 -> fp32 xr.
// ---------------------------------------------------------------------------
#define SMA_HI 0
#define SMA_LO 16384
#define SMB_HI 32768
#define SMB_LO 49152
#define SM_TOT 65536

template <bool PRE>
__global__ void __launch_bounds__(256, 2) k_mma(const float* __restrict__ X,
                                                const unsigned char* __restrict__ Ahi,
                                                const unsigned char* __restrict__ Alo,
                                                const unsigned char* __restrict__ Bhi,
                                                const unsigned char* __restrict__ Blo,
                                                __half2* __restrict__ Y0h,
                                                float* __restrict__ Y1, int N,
                                                const int* __restrict__ ei, int E, int GB) {
    if (!PRE && blockIdx.x >= (unsigned)GB) {
        // scatter side-grid (needs rowptr from k_scan; independent of GEMM)
        for (int i = (blockIdx.x - GB) * 256 + threadIdx.x; i < E; i += 1024 * 256) {
            int d = ei[E + i];
            int p = atomicAdd(&g_fill[d], 1);
            g_adj[p] = ei[i];
        }
        return;
    }
    extern __shared__ char smem[];
    const uint32_t sb = smem_u32(smem);
    const int tid = threadIdx.x, wid = tid >> 5, lane = tid & 31;
    const int rowbase = blockIdx.x * 128;

    const uint4* bh = (const uint4*)Bhi;
    const uint4* bl = (const uint4*)Blo;
#pragma unroll
    for (int i = tid; i < 1024; i += 256) {
        ((uint4*)(smem + SMB_HI))[i] = bh[i];
        ((uint4*)(smem + SMB_LO))[i] = bl[i];
    }
    if (PRE) {
        const uint4* ah = (const uint4*)(Ahi + (size_t)rowbase * 128);
        const uint4* al = (const uint4*)(Alo + (size_t)rowbase * 128);
#pragma unroll
        for (int i = tid; i < 1024; i += 256) {
            ((uint4*)(smem + SMA_HI))[i] = ah[i];
            ((uint4*)(smem + SMA_LO))[i] = al[i];
        }
    } else {
#pragma unroll
        for (int i = tid; i < 4096; i += 256) {
            int r = i >> 5, kp = i & 31;
            int row = rowbase + r;
            float2 v = (row < N) ? *(const float2*)&X[row * 64 + 2 * kp]
                                 : make_float2(0.f, 0.f);
            uint16_t h0, l0, h1, l1;
            bf16_split(v.x, h0, l0);
            bf16_split(v.y, h1, l1);
            uint32_t off = swz_off(r, kp * 4);
            *(uint32_t*)(smem + SMA_HI + off) = (uint32_t)h0 | ((uint32_t)h1 << 16);
            *(uint32_t*)(smem + SMA_LO + off) = (uint32_t)l0 | ((uint32_t)l1 << 16);
        }
    }
    __syncthreads();

    const int m0 = (wid & 3) * 32;
    const int n0 = (wid >> 2) * 64;
    const int rl  = lane & 7;
    const int grp = lane >> 3;

    float acc[2][8][4];
#pragma unroll
    for (int mt = 0; mt < 2; mt++)
#pragma unroll
        for (int nt = 0; nt < 8; nt++)
#pragma unroll
            for (int j = 0; j < 4; j++) acc[mt][nt][j] = 0.f;

#pragma unroll
    for (int ks = 0; ks < 4; ks++) {
        const int cb = ks * 32;
        uint32_t ahi[2][4], alo[2][4];
#pragma unroll
        for (int mt = 0; mt < 2; mt++) {
            int arow = m0 + mt * 16 + (grp & 1) * 8 + rl;
            int abyte = cb + (grp >> 1) * 16;
            ldm_x4(ahi[mt], sb + SMA_HI + swz_off(arow, abyte));
            ldm_x4(alo[mt], sb + SMA_LO + swz_off(arow, abyte));
        }
#pragma unroll
        for (int np = 0; np < 4; np++) {
            int brow = n0 + np * 16 + (grp >> 1) * 8 + rl;
            int bbyte = cb + (grp & 1) * 16;
            uint32_t bhi[4], blo[4];
            ldm_x4(bhi, sb + SMB_HI + swz_off(brow, bbyte));
            ldm_x4(blo, sb + SMB_LO + swz_off(brow, bbyte));
            mma_bf16(acc[0][2 * np],     ahi[0], bhi[0], bhi[1]);
            mma_bf16(acc[1][2 * np],     ahi[1], bhi[0], bhi[1]);
            mma_bf16(acc[0][2 * np + 1], ahi[0], bhi[2], bhi[3]);
            mma_bf16(acc[1][2 * np + 1], ahi[1], bhi[2], bhi[3]);
            mma_bf16(acc[0][2 * np],     alo[0], bhi[0], bhi[1]);
            mma_bf16(acc[1][2 * np],     alo[1], bhi[0], bhi[1]);
            mma_bf16(acc[0][2 * np + 1], alo[0], bhi[2], bhi[3]);
            mma_bf16(acc[1][2 * np + 1], alo[1], bhi[2], bhi[3]);
            mma_bf16(acc[0][2 * np],     ahi[0], blo[0], blo[1]);
            mma_bf16(acc[1][2 * np],     ahi[1], blo[0], blo[1]);
            mma_bf16(acc[0][2 * np + 1], ahi[0], blo[2], blo[3]);
            mma_bf16(acc[1][2 * np + 1], ahi[1], blo[2], blo[3]);
        }
    }

    const int qr = lane >> 2, qc = (lane & 3) * 2;
#pragma unroll
    for (int mt = 0; mt < 2; mt++) {
#pragma unroll
        for (int nt = 0; nt < 8; nt++) {
            int col = n0 + nt * 8 + qc;
            int row0 = rowbase + m0 + mt * 16 + qr;
#pragma unroll
            for (int h = 0; h < 2; h++) {
                int row = row0 + h * 8;
                if (row < N) {
                    float vx = acc[mt][nt][2 * h], vy = acc[mt][nt][2 * h + 1];
                    if (col < 64) Y0h[row * 32 + (col >> 1)] = __floats2half2_rn(vx, vy);
                    else          *(float2*)&Y1[row * 64 + col - 64] = make_float2(vx, vy);
                }
            }
        }
    }
}

// ---------------------------------------------------------------------------
// Layer-3 fused GEMM: Y[128 x 256] = H @ [W3l | W3r], H from pre-split images.
// ---------------------------------------------------------------------------
#define SM3_AHI 0
#define SM3_ALO 16384
#define SM3_BHI 32768
#define SM3_BLO 65536
#define SM3_TOT 98304

__global__ void __launch_bounds__(512) k_mma3(const unsigned char* __restrict__ Ahi,
                                              const unsigned char* __restrict__ Alo,
                                              const unsigned char* __restrict__ Bhi2,
                                              const unsigned char* __restrict__ Blo2,
                                              const unsigned char* __restrict__ Bhi3,
                                              const unsigned char* __restrict__ Blo3,
                                              __half2* __restrict__ Y0h,
                                              float* __restrict__ Y1, int N) {
    extern __shared__ char smem[];
    const uint32_t sb = smem_u32(smem);
    const int tid = threadIdx.x, wid = tid >> 5, lane = tid & 31;
    const int rowbase = blockIdx.x * 128;

#pragma unroll
    for (int i = tid; i < 2048; i += 512) {
        ((uint4*)(smem + SM3_BHI))[i] = (i < 1024) ? ((const uint4*)Bhi2)[i]
                                                   : ((const uint4*)Bhi3)[i - 1024];
        ((uint4*)(smem + SM3_BLO))[i] = (i < 1024) ? ((const uint4*)Blo2)[i]
                                                   : ((const uint4*)Blo3)[i - 1024];
    }
    {
        const uint4* ah = (const uint4*)(Ahi + (size_t)rowbase * 128);
        const uint4* al = (const uint4*)(Alo + (size_t)rowbase * 128);
#pragma unroll
        for (int i = tid; i < 1024; i += 512) {
            ((uint4*)(smem + SM3_AHI))[i] = ah[i];
            ((uint4*)(smem + SM3_ALO))[i] = al[i];
        }
    }
    __syncthreads();

    const int m0 = (wid & 3) * 32;
    const int n0 = (wid >> 2) * 64;  // 0,64,128,192
    const int rl  = lane & 7;
    const int grp = lane >> 3;

    float acc[2][8][4];
#pragma unroll
    for (int mt = 0; mt < 2; mt++)
#pragma unroll
        for (int nt = 0; nt < 8; nt++)
#pragma unroll
            for (int j = 0; j < 4; j++) acc[mt][nt][j] = 0.f;

#pragma unroll
    for (int ks = 0; ks < 4; ks++) {
        const int cb = ks * 32;
        uint32_t ahi[2][4], alo[2][4];
#pragma unroll
        for (int mt = 0; mt < 2; mt++) {
            int arow = m0 + mt * 16 + (grp & 1) * 8 + rl;
            int abyte = cb + (grp >> 1) * 16;
            ldm_x4(ahi[mt], sb + SM3_AHI + swz_off(arow, abyte));
            ldm_x4(alo[mt], sb + SM3_ALO + swz_off(arow, abyte));
        }
#pragma unroll
        for (int np = 0; np < 4; np++) {
            int brow = n0 + np * 16 + (grp >> 1) * 8 + rl;
            int bbyte = cb + (grp & 1) * 16;
            uint32_t bhi[4], blo[4];
            ldm_x4(bhi, sb + SM3_BHI + swz_off(brow, bbyte));
            ldm_x4(blo, sb + SM3_BLO + swz_off(brow, bbyte));
            mma_bf16(acc[0][2 * np],     ahi[0], bhi[0], bhi[1]);
            mma_bf16(acc[1][2 * np],     ahi[1], bhi[0], bhi[1]);
            mma_bf16(acc[0][2 * np + 1], ahi[0], bhi[2], bhi[3]);
            mma_bf16(acc[1][2 * np + 1], ahi[1], bhi[2], bhi[3]);
            mma_bf16(acc[0][2 * np],     alo[0], bhi[0], bhi[1]);
            mma_bf16(acc[1][2 * np],     alo[1], bhi[0], bhi[1]);
            mma_bf16(acc[0][2 * np + 1], alo[0], bhi[2], bhi[3]);
            mma_bf16(acc[1][2 * np + 1], alo[1], bhi[2], bhi[3]);
            mma_bf16(acc[0][2 * np],     ahi[0], blo[0], blo[1]);
            mma_bf16(acc[1][2 * np],     ahi[1], blo[0], blo[1]);
            mma_bf16(acc[0][2 * np + 1], ahi[0], blo[2], blo[3]);
            mma_bf16(acc[1][2 * np + 1], ahi[1], blo[2], blo[3]);
        }
    }

    const int qr = lane >> 2, qc = (lane & 3) * 2;
#pragma unroll
    for (int mt = 0; mt < 2; mt++) {
#pragma unroll
        for (int nt = 0; nt < 8; nt++) {
            int col = n0 + nt * 8 + qc;
            int row0 = rowbase + m0 + mt * 16 + qr;
#pragma unroll
            for (int h = 0; h < 2; h++) {
                int row = row0 + h * 8;
                if (row < N) {
                    float vx = acc[mt][nt][2 * h], vy = acc[mt][nt][2 * h + 1];
                    if (col < 128) Y0h[row * 64 + (col >> 1)] = __floats2half2_rn(vx, vy);
                    else           *(float2*)&Y1[row * 128 + col - 128] = make_float2(vx, vy);
                }
            }
        }
    }
}

// ---------------------------------------------------------------------------
// Edge phase (half2 score + half2 quad partial sums; fp32 softmax state)
// ---------------------------------------------------------------------------
__device__ __forceinline__ float red8(float p) {
    p += __shfl_xor_sync(0xffffffffu, p, 4);
    p += __shfl_xor_sync(0xffffffffu, p, 2);
    p += __shfl_xor_sync(0xffffffffu, p, 1);
    return p;
}
__device__ __forceinline__ float red4(float p) {
    p += __shfl_xor_sync(0xffffffffu, p, 2);
    p += __shfl_xor_sync(0xffffffffu, p, 1);
    return p;
}

// half2 score: a0*leaky(v0+xr0) summed over the lane's 4 features
__device__ __forceinline__ float hscore(__half2 vh0, __half2 vh1,
                                        __half2 xrh0, __half2 xrh1,
                                        __half2 ah0, __half2 ah1, __half2 c02) {
    __half2 t0 = __hadd2(vh0, xrh0);
    __half2 t1 = __hadd2(vh1, xrh1);
    t0 = __hmax2(t0, __hmul2(t0, c02));
    t1 = __hmax2(t1, __hmul2(t1, c02));
    __half2 s2 = __hfma2(ah1, t1, __hmul2(ah0, t0));
    return __half2float(__hadd(__low2half(s2), __high2half(s2)));
}

// k_edge64: two nodes per warp (16 lanes each, 4 fp16 feats/lane), 4-edge
// pipeline with UNCONDITIONAL adjacency prefetch, quad-merged online softmax,
// half2 score + half2 weighted partial sums.
__global__ void k_edge64(const __half2* __restrict__ XLH, const float* __restrict__ XR,
                         const float* __restrict__ att, const float* __restrict__ bias,
                         uint2* __restrict__ OHI, uint2* __restrict__ OLO, int N) {
    const int lane = threadIdx.x & 31;
    const int hl   = lane & 15;
    const int wg   = (blockIdx.x * blockDim.x + threadIdx.x) >> 5;
    const int n    = wg * 2 + (lane >> 4);
    const bool valid = n < N;
    const int nc = valid ? n : N - 1;

    const uint2* XL2 = (const uint2*)XLH;
    const __half2 c02 = __float2half2_rn(0.2f);

    float4 a  = *(const float4*)&att[4 * hl];
    __half2 ah0 = __floats2half2_rn(a.x, a.y), ah1 = __floats2half2_rn(a.z, a.w);
    float4 xr = *(const float4*)&XR[nc * 64 + 4 * hl];
    __half2 xrh0 = __floats2half2_rn(xr.x, xr.y), xrh1 = __floats2half2_rn(xr.z, xr.w);

    uint2 su = XL2[nc * 16 + hl];
    __half2 svh0 = *(__half2*)&su.x, svh1 = *(__half2*)&su.y;
    float2 sf0 = __half22float2(svh0), sf1 = __half22float2(svh1);
    float4 acc = make_float4(sf0.x, sf0.y, sf1.x, sf1.y);

    float m = red4(hscore(svh0, svh1, xrh0, xrh1, ah0, ah1, c02));
    float d = 1.f;

    int beg = g_rowptr[nc];
    int end = valid ? g_rowptr[nc + 1] : beg;
    int cnt = end - beg;
    int ocnt = __shfl_xor_sync(0xffffffffu, cnt, 16);
    int nq = (max(cnt, ocnt) + 3) >> 2;

    int j = beg;
    int s0 = g_adj[j], s1 = g_adj[j + 1], s2 = g_adj[j + 2], s3 = g_adj[j + 3];

    for (int q = 0; q < nq; q++) {
        uint2 u0 = XL2[s0 * 16 + hl];
        uint2 u1 = XL2[s1 * 16 + hl];
        uint2 u2 = XL2[s2 * 16 + hl];
        uint2 u3 = XL2[s3 * 16 + hl];
        int rem = end - j;
        j += 4;
        s0 = g_adj[j]; s1 = g_adj[j + 1]; s2 = g_adj[j + 2]; s3 = g_adj[j + 3];

        __half2 v0h0 = *(__half2*)&u0.x, v0h1 = *(__half2*)&u0.y;
        __half2 v1h0 = *(__half2*)&u1.x, v1h1 = *(__half2*)&u1.y;
        __half2 v2h0 = *(__half2*)&u2.x, v2h1 = *(__half2*)&u2.y;
        __half2 v3h0 = *(__half2*)&u3.x, v3h1 = *(__half2*)&u3.y;

        float p0 = red4(hscore(v0h0, v0h1, xrh0, xrh1, ah0, ah1, c02));
        float p1 = red4(hscore(v1h0, v1h1, xrh0, xrh1, ah0, ah1, c02));
        float p2 = red4(hscore(v2h0, v2h1, xrh0, xrh1, ah0, ah1, c02));
        float p3 = red4(hscore(v3h0, v3h1, xrh0, xrh1, ah0, ah1, c02));
        p0 = (0 < rem) ? p0 : -1e30f;
        p1 = (1 < rem) ? p1 : -1e30f;
        p2 = (2 < rem) ? p2 : -1e30f;
        p3 = (3 < rem) ? p3 : -1e30f;

        float mq = fmaxf(fmaxf(p0, p1), fmaxf(p2, p3));
        float mn = fmaxf(m, mq);
        float w  = __expf(m - mn);
        float e0 = __expf(p0 - mn), e1 = __expf(p1 - mn);
        float e2 = __expf(p2 - mn), e3 = __expf(p3 - mn);

        __half2 eh0 = __float2half2_rn(e0), eh1 = __float2half2_rn(e1);
        __half2 eh2 = __float2half2_rn(e2), eh3 = __float2half2_rn(e3);
        __half2 sum0 = __hmul2(eh0, v0h0);
        sum0 = __hfma2(eh1, v1h0, sum0);
        sum0 = __hfma2(eh2, v2h0, sum0);
        sum0 = __hfma2(eh3, v3h0, sum0);
        __half2 sum1 = __hmul2(eh0, v0h1);
        sum1 = __hfma2(eh1, v1h1, sum1);
        sum1 = __hfma2(eh2, v2h1, sum1);
        sum1 = __hfma2(eh3, v3h1, sum1);
        float2 g0 = __half22float2(sum0), g1 = __half22float2(sum1);
        acc.x = acc.x * w + g0.x;
        acc.y = acc.y * w + g0.y;
        acc.z = acc.z * w + g1.x;
        acc.w = acc.w * w + g1.y;
        d = d * w + ((e0 + e1) + (e2 + e3));
        m = mn;
    }
    float inv = 1.f / d;
    float o0 = acc.x * inv + bias[4 * hl + 0];
    float o1 = acc.y * inv + bias[4 * hl + 1];
    float o2 = acc.z * inv + bias[4 * hl + 2];
    float o3 = acc.w * inv + bias[4 * hl + 3];
    o0 = o0 > 0.f ? o0 : (__expf(o0) - 1.f);
    o1 = o1 > 0.f ? o1 : (__expf(o1) - 1.f);
    o2 = o2 > 0.f ? o2 : (__expf(o2) - 1.f);
    o3 = o3 > 0.f ? o3 : (__expf(o3) - 1.f);
    if (valid) {
        uint16_t h0, l0, h1, l1, h2, l2, h3, l3;
        bf16_split(o0, h0, l0);
        bf16_split(o1, h1, l1);
        bf16_split(o2, h2, l2);
        bf16_split(o3, h3, l3);
        int idx = n * 16 + (hl ^ ((n & 7) << 1));   // swizzled 8B-unit offset
        OHI[idx] = make_uint2((uint32_t)h0 | ((uint32_t)h1 << 16),
                              (uint32_t)h2 | ((uint32_t)h3 << 16));
        OLO[idx] = make_uint2((uint32_t)l0 | ((uint32_t)l1 << 16),
                              (uint32_t)l2 | ((uint32_t)l3 << 16));
    }
}

// k_edge128_mean: masked nq-loop, half2 score/partials, mean over heads.
__global__ void k_edge128_mean(const __half2* __restrict__ XLH, const float* __restrict__ XR,
                               const float* __restrict__ att, const float* __restrict__ bias,
                               float* __restrict__ OUT, int N) {
    int lane = threadIdx.x & 31;
    int n    = (blockIdx.x * blockDim.x + threadIdx.x) >> 5;
    if (n >= N) return;

    const __half2 c02 = __float2half2_rn(0.2f);
    float4 a  = *(const float4*)&att[4 * lane];
    __half2 ah0 = __floats2half2_rn(a.x, a.y), ah1 = __floats2half2_rn(a.z, a.w);
    float4 xr = *(const float4*)&XR[n * 128 + 4 * lane];
    __half2 xrh0 = __floats2half2_rn(xr.x, xr.y), xrh1 = __floats2half2_rn(xr.z, xr.w);

    uint2 su = *(const uint2*)&XLH[n * 64 + 2 * lane];
    __half2 svh0 = *(__half2*)&su.x, svh1 = *(__half2*)&su.y;
    float2 sf0 = __half22float2(svh0), sf1 = __half22float2(svh1);
    float4 acc = make_float4(sf0.x, sf0.y, sf1.x, sf1.y);

    float m = red8(hscore(svh0, svh1, xrh0, xrh1, ah0, ah1, c02));
    float d = 1.f;

    int beg = g_rowptr[n], end = g_rowptr[n + 1];
    int nq = (end - beg + 3) >> 2;
    int j = beg;
    int s0 = g_adj[j], s1 = g_adj[j + 1], s2 = g_adj[j + 2], s3 = g_adj[j + 3];

    for (int q = 0; q < nq; q++) {
        uint2 u0 = *(const uint2*)&XLH[s0 * 64 + 2 * lane];
        uint2 u1 = *(const uint2*)&XLH[s1 * 64 + 2 * lane];
        uint2 u2 = *(const uint2*)&XLH[s2 * 64 + 2 * lane];
        uint2 u3 = *(const uint2*)&XLH[s3 * 64 + 2 * lane];
        int rem = end - j;
        j += 4;
        s0 = g_adj[j]; s1 = g_adj[j + 1]; s2 = g_adj[j + 2]; s3 = g_adj[j + 3];

        __half2 v0h0 = *(__half2*)&u0.x, v0h1 = *(__half2*)&u0.y;
        __half2 v1h0 = *(__half2*)&u1.x, v1h1 = *(__half2*)&u1.y;
        __half2 v2h0 = *(__half2*)&u2.x, v2h1 = *(__half2*)&u2.y;
        __half2 v3h0 = *(__half2*)&u3.x, v3h1 = *(__half2*)&u3.y;

        float p0 = red8(hscore(v0h0, v0h1, xrh0, xrh1, ah0, ah1, c02));
        float p1 = red8(hscore(v1h0, v1h1, xrh0, xrh1, ah0, ah1, c02));
        float p2 = red8(hscore(v2h0, v2h1, xrh0, xrh1, ah0, ah1, c02));
        float p3 = red8(hscore(v3h0, v3h1, xrh0, xrh1, ah0, ah1, c02));
        p0 = (0 < rem) ? p0 : -1e30f;
        p1 = (1 < rem) ? p1 : -1e30f;
        p2 = (2 < rem) ? p2 : -1e30f;
        p3 = (3 < rem) ? p3 : -1e30f;

        float mq = fmaxf(fmaxf(p0, p1), fmaxf(p2, p3));
        float mn = fmaxf(m, mq);
        float w  = __expf(m - mn);
        float e0 = __expf(p0 - mn), e1 = __expf(p1 - mn);
        float e2 = __expf(p2 - mn), e3 = __expf(p3 - mn);

        __half2 eh0 = __float2half2_rn(e0), eh1 = __float2half2_rn(e1);
        __half2 eh2 = __float2half2_rn(e2), eh3 = __float2half2_rn(e3);
        __half2 sum0 = __hmul2(eh0, v0h0);
        sum0 = __hfma2(eh1, v1h0, sum0);
        sum0 = __hfma2(eh2, v2h0, sum0);
        sum0 = __hfma2(eh3, v3h0, sum0);
        __half2 sum1 = __hmul2(eh0, v0h1);
        sum1 = __hfma2(eh1, v1h1, sum1);
        sum1 = __hfma2(eh2, v2h1, sum1);
        sum1 = __hfma2(eh3, v3h1, sum1);
        float2 g0 = __half22float2(sum0), g1 = __half22float2(sum1);
        acc.x = acc.x * w + g0.x;
        acc.y = acc.y * w + g0.y;
        acc.z = acc.z * w + g1.x;
        acc.w = acc.w * w + g1.y;
        d = d * w + ((e0 + e1) + (e2 + e3));
        m = mn;
    }
    float inv = 1.f / d;
    float o0 = acc.x * inv, o1 = acc.y * inv, o2 = acc.z * inv, o3 = acc.w * inv;
#pragma unroll
    for (int off = 8; off <= 16; off <<= 1) {
        o0 += __shfl_xor_sync(0xffffffffu, o0, off);
        o1 += __shfl_xor_sync(0xffffffffu, o1, off);
        o2 += __shfl_xor_sync(0xffffffffu, o2, off);
        o3 += __shfl_xor_sync(0xffffffffu, o3, off);
    }
    if (lane < 8) {
        int c = 4 * lane;
        float4 o = make_float4(0.25f * o0 + bias[c + 0],
                               0.25f * o1 + bias[c + 1],
                               0.25f * o2 + bias[c + 2],
                               0.25f * o3 + bias[c + 3]);
        *(float4*)&OUT[n * 32 + c] = o;
    }
}

// ---------------------------------------------------------------------------
// Launch: k_hist -> k_scan -> [GEMM1 ‖ scatter] -> edges/GEMMs
// ---------------------------------------------------------------------------
extern "C" void kernel_launch(void* const* d_in, const int* in_sizes, int n_in,
                              void* d_out, int out_size) {
    const float* x   = (const float*)d_in[0];
    const int*   ei  = (const int*)  d_in[1];
    const float* W1l = (const float*)d_in[2];
    const float* W1r = (const float*)d_in[3];
    const float* a1  = (const float*)d_in[4];
    const float* b1  = (const float*)d_in[5];
    const float* W2l = (const float*)d_in[6];
    const float* W2r = (const float*)d_in[7];
    const float* a2  = (const float*)d_in[8];
    const float* b2  = (const float*)d_in[9];
    const float* W3l = (const float*)d_in[10];
    const float* W3r = (const float*)d_in[11];
    const float* a3  = (const float*)d_in[12];
    const float* b3  = (const float*)d_in[13];
    float* out = (float*)d_out;

    const int N = in_sizes[0] / 64;
    const int E = in_sizes[1] / 2;
    const int NB = (N + 1023) / 1024;

    float *xlf, *xr;
    unsigned char *hhi, *hlo;
    unsigned char (*whi)[16384], (*wlo)[16384];
    cudaGetSymbolAddress((void**)&xlf, g_xl);
    cudaGetSymbolAddress((void**)&xr,  g_xr);
    cudaGetSymbolAddress((void**)&hhi, g_hhi);
    cudaGetSymbolAddress((void**)&hlo, g_hlo);
    cudaGetSymbolAddress((void**)&whi, g_wimg_hi);
    cudaGetSymbolAddress((void**)&wlo, g_wimg_lo);
    __half2* xlh = (__half2*)xlf;

    cudaFuncSetAttribute(k_mma<false>, cudaFuncAttributeMaxDynamicSharedMemorySize, SM_TOT);
    cudaFuncSetAttribute(k_mma<true>,  cudaFuncAttributeMaxDynamicSharedMemorySize, SM_TOT);
    cudaFuncSetAttribute(k_mma3, cudaFuncAttributeMaxDynamicSharedMemorySize, SM3_TOT);

    const int GT  = (N + 127) / 128;
    const int EB  = (N + 15) / 16;    // edge64: 8 warps x 2 nodes per block
    const int EBM = (N + 7) / 8;      // edge128: 8 warps x 1 node per block

    // 0: W images + edge histogram + bsum zero
    k_hist<<<64 + 1024, 256>>>(ei, E, W1l, W1r, W2l, W2r, W3l, W3r);
    // 1: fused decoupled-lookback scan (also re-zeroes g_cnt)
    k_scan<<<NB, 1024>>>(N, E);
    // 2: layer-1 GEMM + scatter side-grid
    k_mma<false><<<GT + 1024, 256, SM_TOT>>>(x, nullptr, nullptr, whi[0], wlo[0],
                                             xlh, xr, N, ei, E, GT);
    // 3: layer-1 edge -> pre-split h images
    k_edge64<<<EB, 256>>>(xlh, xr, a1, b1, (uint2*)hhi, (uint2*)hlo, N);
    // 4: layer-2 GEMM (pre-split A)
    k_mma<true><<<GT, 256, SM_TOT>>>(nullptr, hhi, hlo, whi[1], wlo[1],
                                     xlh, xr, N, nullptr, 0, GT);
    // 5: layer-2 edge
    k_edge64<<<EB, 256>>>(xlh, xr, a2, b2, (uint2*)hhi, (uint2*)hlo, N);
    // 6: layer-3 fused dual-N GEMM (pre-split A)
    k_mma3<<<GT, 512, SM3_TOT>>>(hhi, hlo, whi[2], wlo[2], whi[3], wlo[3], xlh, xr, N);
    // 7: layer-3 edge (mean over heads) -> final output
    k_edge128_mean<<<EBM, 256>>>(xlh, xr, a3, b3, out, N);
}